// round 5
// baseline (speedup 1.0000x reference)
#include <cuda_runtime.h>
#include <math.h>

#define BB 2
#define SS 2048
#define EE 1024
#define HH 16
#define DD 64
#define MROWS (BB*SS)          // 4096

// ---- scratch (device globals: allocation-free rule) ----
__device__ float g_qkv[(size_t)MROWS * 3 * EE];      // 50.3 MB
__device__ float g_q[(size_t)BB * HH * SS * DD];     // 16.8 MB
__device__ float g_k[(size_t)BB * HH * SS * DD];
__device__ float g_v[(size_t)BB * HH * SS * DD];
__device__ float g_y[(size_t)MROWS * EE];
__device__ float g_cos[SS * (DD/2)];
__device__ float g_sin[SS * (DD/2)];

// ---------------- RoPE tables (double precision sincos, fast-math safe) ----
__global__ void rope_tables_kernel() {
    int idx = blockIdx.x * blockDim.x + threadIdx.x;   // SS*32 threads
    if (idx >= SS * 32) return;
    int i = idx & 31;
    int s = idx >> 5;
    float theta = (float)exp(-2.0 * (double)i / 64.0 * log(10000.0));
    float freq  = (float)s * theta;     // fp32 product, as in reference
    double fr = (double)freq;
    g_cos[idx] = (float)cos(fr);
    g_sin[idx] = (float)sin(fr);
}

// ---------------- classic 128x128x8 SGEMM, C[m,n] = sum_k A[m,k]*B[n,k] ----
// A_FROM_Y: A comes from g_y (ignore Aparam).  C_TO_QKV: C goes to g_qkv.
template<bool A_FROM_Y, bool C_TO_QKV>
__global__ void __launch_bounds__(256)
sgemm_nt(const float* __restrict__ Aparam, const float* __restrict__ B,
         float* __restrict__ Cparam, int M, int N, int K) {
    const float* A = A_FROM_Y ? (const float*)g_y : Aparam;
    float*       C = C_TO_QKV ? (float*)g_qkv : Cparam;

    __shared__ float As[8][128];
    __shared__ float Bs[8][128];
    const int tid = threadIdx.x;
    const int bm = blockIdx.y * 128;
    const int bn = blockIdx.x * 128;
    const int lr = tid >> 1;               // 0..127
    const int lk = (tid & 1) << 2;         // 0 or 4
    const float* Ap = A + (size_t)(bm + lr) * K + lk;
    const float* Bp = B + (size_t)(bn + lr) * K + lk;
    const int tx = tid & 15;
    const int ty = tid >> 4;

    float acc[8][8];
    #pragma unroll
    for (int i = 0; i < 8; i++)
        #pragma unroll
        for (int j = 0; j < 8; j++) acc[i][j] = 0.f;

    for (int k0 = 0; k0 < K; k0 += 8) {
        float4 a4 = *(const float4*)(Ap + k0);
        float4 b4 = *(const float4*)(Bp + k0);
        __syncthreads();
        As[lk+0][lr] = a4.x; As[lk+1][lr] = a4.y;
        As[lk+2][lr] = a4.z; As[lk+3][lr] = a4.w;
        Bs[lk+0][lr] = b4.x; Bs[lk+1][lr] = b4.y;
        Bs[lk+2][lr] = b4.z; Bs[lk+3][lr] = b4.w;
        __syncthreads();
        #pragma unroll
        for (int kk = 0; kk < 8; kk++) {
            float ar[8], br[8];
            *(float4*)(ar)   = *(const float4*)(&As[kk][ty*8]);
            *(float4*)(ar+4) = *(const float4*)(&As[kk][ty*8+4]);
            *(float4*)(br)   = *(const float4*)(&Bs[kk][tx*8]);
            *(float4*)(br+4) = *(const float4*)(&Bs[kk][tx*8+4]);
            #pragma unroll
            for (int i = 0; i < 8; i++)
                #pragma unroll
                for (int j = 0; j < 8; j++)
                    acc[i][j] += ar[i] * br[j];
        }
    }
    #pragma unroll
    for (int i = 0; i < 8; i++) {
        float* crow = C + (size_t)(bm + ty*8 + i) * N + bn + tx*8;
        *(float4*)(crow)   = make_float4(acc[i][0], acc[i][1], acc[i][2], acc[i][3]);
        *(float4*)(crow+4) = make_float4(acc[i][4], acc[i][5], acc[i][6], acc[i][7]);
    }
}

// ---------------- RoPE apply + split qkv -> q,k,v in [B,H,S,D] -------------
__global__ void rope_split_kernel() {
    int idx = blockIdx.x * 256 + threadIdx.x;   // BB*SS*HH*32 total
    const int i = idx & 31;
    const int h = (idx >> 5) & 15;
    const int s = (idx >> 9) & (SS - 1);
    const int b = idx >> 20;
    const float c  = g_cos[(s << 5) + i];
    const float sn = g_sin[(s << 5) + i];
    const float* row = g_qkv + (size_t)(b * SS + s) * (3 * EE);
    const float2 qp = ((const float2*)(row          ))[(h << 5) + i];
    const float2 kp = ((const float2*)(row +     EE))[(h << 5) + i];
    const float2 vp = ((const float2*)(row + 2 * EE))[(h << 5) + i];
    const size_t base2 = (size_t)((b * HH + h) * SS + s) * 32 + i;
    ((float2*)g_q)[base2] = make_float2(qp.x * c - qp.y * sn, qp.x * sn + qp.y * c);
    ((float2*)g_k)[base2] = make_float2(kp.x * c - kp.y * sn, kp.x * sn + kp.y * c);
    ((float2*)g_v)[base2] = vp;
}

// ---------------- causal flash attention, fp32, Bq=64 Bk=32 ----------------
// Q,K,V: [B*H, S, 64] (g_q,g_k,g_v).  Y = g_y: [B, S, E], head slice h*64.
__global__ void __launch_bounds__(256)
flash_kernel() {
    const int qt = (int)gridDim.x - 1 - (int)blockIdx.x;  // big tiles first
    const int bh = blockIdx.y;
    const int b = bh >> 4;
    const int h = bh & 15;
    const int tid = threadIdx.x;
    const int tx = tid & 15;
    const int ty = tid >> 4;

    __shared__ float Qt[64][64];      // [d][r]  (transposed)
    __shared__ float KVs[2048];       // K: [d][c] stride 32; then V: [c][d] stride 64
    __shared__ float Pst[32][68];     // [c][r]  (transposed, padded stride)

    // load Q tile transposed
    {
        const int r  = tid >> 2;
        const int d0 = (tid & 3) << 4;
        const float* qrow = g_q + ((size_t)bh * SS + (size_t)qt * 64 + r) * DD + d0;
        #pragma unroll
        for (int u = 0; u < 16; u += 4) {
            float4 q4 = *(const float4*)(qrow + u);
            Qt[d0+u+0][r] = q4.x; Qt[d0+u+1][r] = q4.y;
            Qt[d0+u+2][r] = q4.z; Qt[d0+u+3][r] = q4.w;
        }
    }

    float o[4][4];
    float m_i[4], l_i[4];
    #pragma unroll
    for (int i = 0; i < 4; i++) {
        m_i[i] = -1e30f; l_i[i] = 0.f;
        #pragma unroll
        for (int j = 0; j < 4; j++) o[i][j] = 0.f;
    }

    const int nkt = 2 * qt + 2;
    for (int kt = 0; kt < nkt; kt++) {
        __syncthreads();   // prior V reads done (and Q store visible on iter 0)
        // K tile, transposed [d][c], stride 32
        {
            const int c  = tid >> 3;
            const int d0 = (tid & 7) << 3;
            const float* krow = g_k + ((size_t)bh * SS + (size_t)kt * 32 + c) * DD + d0;
            #pragma unroll
            for (int u = 0; u < 8; u += 4) {
                float4 k4 = *(const float4*)(krow + u);
                KVs[(d0+u+0)*32 + c] = k4.x;
                KVs[(d0+u+1)*32 + c] = k4.y;
                KVs[(d0+u+2)*32 + c] = k4.z;
                KVs[(d0+u+3)*32 + c] = k4.w;
            }
        }
        __syncthreads();

        // scores: rows ty*4+i, key cols tx*2+j
        float sc[4][2] = {{0.f,0.f},{0.f,0.f},{0.f,0.f},{0.f,0.f}};
        #pragma unroll 16
        for (int d = 0; d < 64; d++) {
            const float4 q4 = *(const float4*)(&Qt[d][ty << 2]);
            const float k0 = KVs[d*32 + (tx << 1)];
            const float k1 = KVs[d*32 + (tx << 1) + 1];
            sc[0][0] += q4.x*k0; sc[0][1] += q4.x*k1;
            sc[1][0] += q4.y*k0; sc[1][1] += q4.y*k1;
            sc[2][0] += q4.z*k0; sc[2][1] += q4.z*k1;
            sc[3][0] += q4.w*k0; sc[3][1] += q4.w*k1;
        }

        // scale + causal mask
        const int kc0 = kt*32 + (tx << 1);
        #pragma unroll
        for (int i = 0; i < 4; i++) {
            const int qr = qt*64 + (ty << 2) + i;
            #pragma unroll
            for (int j = 0; j < 2; j++) {
                float s = sc[i][j] * 0.125f;
                sc[i][j] = (kc0 + j > qr) ? -1e30f : s;
            }
        }

        // online softmax (state in registers, 16-lane shfl reductions)
        float p[4][2];
        #pragma unroll
        for (int i = 0; i < 4; i++) {
            float mx = fmaxf(sc[i][0], sc[i][1]);
            #pragma unroll
            for (int off = 8; off > 0; off >>= 1)
                mx = fmaxf(mx, __shfl_xor_sync(0xffffffffu, mx, off));
            const float mnew = fmaxf(m_i[i], mx);
            p[i][0] = __expf(sc[i][0] - mnew);
            p[i][1] = __expf(sc[i][1] - mnew);
            float rs = p[i][0] + p[i][1];
            #pragma unroll
            for (int off = 8; off > 0; off >>= 1)
                rs += __shfl_xor_sync(0xffffffffu, rs, off);
            const float al = __expf(m_i[i] - mnew);
            l_i[i] = l_i[i] * al + rs;
            m_i[i] = mnew;
            o[i][0] *= al; o[i][1] *= al; o[i][2] *= al; o[i][3] *= al;
        }

        // write P transposed (each thread owns a 4-row column -> sts.128)
        *(float4*)(&Pst[(tx<<1)+0][ty<<2]) = make_float4(p[0][0], p[1][0], p[2][0], p[3][0]);
        *(float4*)(&Pst[(tx<<1)+1][ty<<2]) = make_float4(p[0][1], p[1][1], p[2][1], p[3][1]);

        __syncthreads();  // P visible, K reads done -> safe to overwrite with V
        // V tile, row-major [c][d], stride 64
        {
            const int c  = tid >> 3;
            const int d0 = (tid & 7) << 3;
            const float* vrow = g_v + ((size_t)bh * SS + (size_t)kt * 32 + c) * DD + d0;
            #pragma unroll
            for (int u = 0; u < 8; u += 4)
                *(float4*)(&KVs[c*64 + d0 + u]) = *(const float4*)(vrow + u);
        }
        __syncthreads();

        // O += P @ V  (d cols tx*4+j)
        #pragma unroll
        for (int c = 0; c < 32; c++) {
            const float4 pv = *(const float4*)(&Pst[c][ty << 2]);
            const float4 vv = *(const float4*)(&KVs[c*64 + (tx << 2)]);
            o[0][0] += pv.x*vv.x; o[0][1] += pv.x*vv.y; o[0][2] += pv.x*vv.z; o[0][3] += pv.x*vv.w;
            o[1][0] += pv.y*vv.x; o[1][1] += pv.y*vv.y; o[1][2] += pv.y*vv.z; o[1][3] += pv.y*vv.w;
            o[2][0] += pv.z*vv.x; o[2][1] += pv.z*vv.y; o[2][2] += pv.z*vv.z; o[2][3] += pv.z*vv.w;
            o[3][0] += pv.w*vv.x; o[3][1] += pv.w*vv.y; o[3][2] += pv.w*vv.z; o[3][3] += pv.w*vv.w;
        }
    }

    #pragma unroll
    for (int i = 0; i < 4; i++) {
        const float inv = 1.f / l_i[i];
        const int qr = qt*64 + (ty << 2) + i;
        float* yrow = g_y + ((size_t)b * SS + qr) * EE + h * DD + (tx << 2);
        *(float4*)yrow = make_float4(o[i][0]*inv, o[i][1]*inv, o[i][2]*inv, o[i][3]*inv);
    }
}

// ---------------- launch --------------------------------------------------
extern "C" void kernel_launch(void* const* d_in, const int* in_sizes, int n_in,
                              void* d_out, int out_size) {
    (void)in_sizes; (void)n_in; (void)out_size;
    const float* x    = (const float*)d_in[0];
    const float* Wqkv = (const float*)d_in[1];
    const float* Wo   = (const float*)d_in[2];
    float* out = (float*)d_out;

    rope_tables_kernel<<<(SS*32 + 255)/256, 256>>>();
    // x @ Wqkv^T -> g_qkv
    sgemm_nt<false, true><<<dim3(3*EE/128, MROWS/128), 256>>>(x, Wqkv, nullptr, MROWS, 3*EE, EE);
    rope_split_kernel<<<(BB*SS*HH*32)/256, 256>>>();
    flash_kernel<<<dim3(SS/64, BB*HH), 256>>>();
    // g_y @ Wo^T -> out
    sgemm_nt<true, false><<<dim3(EE/128, MROWS/128), 256>>>(nullptr, Wo, out, MROWS, EE, EE);
}

// round 6
// speedup vs baseline: 1.0507x; 1.0507x over previous
#include <cuda_runtime.h>
#include <math.h>

#define BB 2
#define SS 2048
#define EE 1024
#define HH 16
#define DD 64
#define MROWS (BB*SS)          // 4096

// ---- scratch (device globals: allocation-free rule) ----
__device__ float g_qkv[(size_t)MROWS * 3 * EE];      // 50.3 MB
__device__ float g_q[(size_t)BB * HH * SS * DD];     // 16.8 MB
__device__ float g_k[(size_t)BB * HH * SS * DD];
__device__ float g_v[(size_t)BB * HH * SS * DD];
__device__ float g_y[(size_t)MROWS * EE];
__device__ float g_cos[SS * (DD/2)];
__device__ float g_sin[SS * (DD/2)];

// ---------------- RoPE tables (double precision sincos, fast-math safe) ----
__global__ void rope_tables_kernel() {
    int idx = blockIdx.x * blockDim.x + threadIdx.x;   // SS*32 threads
    if (idx >= SS * 32) return;
    int i = idx & 31;
    int s = idx >> 5;
    float theta = (float)exp(-2.0 * (double)i / 64.0 * log(10000.0));
    float freq  = (float)s * theta;     // fp32 product, as in reference
    double fr = (double)freq;
    g_cos[idx] = (float)cos(fr);
    g_sin[idx] = (float)sin(fr);
}

// ---------------- classic 128x128x8 SGEMM, C[m,n] = sum_k A[m,k]*B[n,k] ----
template<bool A_FROM_Y, bool C_TO_QKV>
__global__ void __launch_bounds__(256)
sgemm_nt(const float* __restrict__ Aparam, const float* __restrict__ B,
         float* __restrict__ Cparam, int M, int N, int K) {
    const float* A = A_FROM_Y ? (const float*)g_y : Aparam;
    float*       C = C_TO_QKV ? (float*)g_qkv : Cparam;

    __shared__ float As[8][128];
    __shared__ float Bs[8][128];
    const int tid = threadIdx.x;
    const int bm = blockIdx.y * 128;
    const int bn = blockIdx.x * 128;
    const int lr = tid >> 1;               // 0..127
    const int lk = (tid & 1) << 2;         // 0 or 4
    const float* Ap = A + (size_t)(bm + lr) * K + lk;
    const float* Bp = B + (size_t)(bn + lr) * K + lk;
    const int tx = tid & 15;
    const int ty = tid >> 4;

    float acc[8][8];
    #pragma unroll
    for (int i = 0; i < 8; i++)
        #pragma unroll
        for (int j = 0; j < 8; j++) acc[i][j] = 0.f;

    for (int k0 = 0; k0 < K; k0 += 8) {
        float4 a4 = *(const float4*)(Ap + k0);
        float4 b4 = *(const float4*)(Bp + k0);
        __syncthreads();
        As[lk+0][lr] = a4.x; As[lk+1][lr] = a4.y;
        As[lk+2][lr] = a4.z; As[lk+3][lr] = a4.w;
        Bs[lk+0][lr] = b4.x; Bs[lk+1][lr] = b4.y;
        Bs[lk+2][lr] = b4.z; Bs[lk+3][lr] = b4.w;
        __syncthreads();
        #pragma unroll
        for (int kk = 0; kk < 8; kk++) {
            float ar[8], br[8];
            *(float4*)(ar)   = *(const float4*)(&As[kk][ty*8]);
            *(float4*)(ar+4) = *(const float4*)(&As[kk][ty*8+4]);
            *(float4*)(br)   = *(const float4*)(&Bs[kk][tx*8]);
            *(float4*)(br+4) = *(const float4*)(&Bs[kk][tx*8+4]);
            #pragma unroll
            for (int i = 0; i < 8; i++)
                #pragma unroll
                for (int j = 0; j < 8; j++)
                    acc[i][j] += ar[i] * br[j];
        }
    }
    #pragma unroll
    for (int i = 0; i < 8; i++) {
        float* crow = C + (size_t)(bm + ty*8 + i) * N + bn + tx*8;
        *(float4*)(crow)   = make_float4(acc[i][0], acc[i][1], acc[i][2], acc[i][3]);
        *(float4*)(crow+4) = make_float4(acc[i][4], acc[i][5], acc[i][6], acc[i][7]);
    }
}

// ---------------- RoPE apply + split qkv -> q,k,v in [B,H,S,D] -------------
__global__ void rope_split_kernel() {
    int idx = blockIdx.x * 256 + threadIdx.x;   // BB*SS*HH*32 total
    const int i = idx & 31;
    const int h = (idx >> 5) & 15;
    const int s = (idx >> 9) & (SS - 1);
    const int b = idx >> 20;
    const float c  = g_cos[(s << 5) + i];
    const float sn = g_sin[(s << 5) + i];
    const float* row = g_qkv + (size_t)(b * SS + s) * (3 * EE);
    const float2 qp = ((const float2*)(row          ))[(h << 5) + i];
    const float2 kp = ((const float2*)(row +     EE))[(h << 5) + i];
    const float2 vp = ((const float2*)(row + 2 * EE))[(h << 5) + i];
    const size_t base2 = (size_t)((b * HH + h) * SS + s) * 32 + i;
    ((float2*)g_q)[base2] = make_float2(qp.x * c - qp.y * sn, qp.x * sn + qp.y * c);
    ((float2*)g_k)[base2] = make_float2(kp.x * c - kp.y * sn, kp.x * sn + kp.y * c);
    ((float2*)g_v)[base2] = vp;
}

// ---------------- causal flash attention, fp32, Bq=64 Bk=64 ----------------
// Q,K,V: [B*H, S, 64] (g_q,g_k,g_v).  Y = g_y: [B, S, E], head slice h*64.
// 256 threads, 4x4 microtile: tx (0..15) -> key/d cols, ty (0..15) -> q rows.
__global__ void __launch_bounds__(256)
flash_kernel() {
    const int qt = (int)gridDim.x - 1 - (int)blockIdx.x;  // big tiles first
    const int bh = blockIdx.y;
    const int b = bh >> 4;
    const int h = bh & 15;
    const int tid = threadIdx.x;
    const int tx = tid & 15;
    const int ty = tid >> 4;

    __shared__ float Qt[64][64];      // [d][r]  (transposed, pre-scaled)
    __shared__ float KVs[64*64];      // K: [d][c] stride 64; then V: [c][d] stride 64
    __shared__ float Pst[64][64];     // [c][rot-swizzled r]

    // load Q tile transposed, fold in 1/sqrt(D) = 0.125
    {
        const int r  = tid >> 2;
        const int d0 = (tid & 3) << 4;
        const float* qrow = g_q + ((size_t)bh * SS + (size_t)qt * 64 + r) * DD + d0;
        #pragma unroll
        for (int u = 0; u < 16; u += 4) {
            float4 q4 = *(const float4*)(qrow + u);
            Qt[d0+u+0][r] = q4.x * 0.125f; Qt[d0+u+1][r] = q4.y * 0.125f;
            Qt[d0+u+2][r] = q4.z * 0.125f; Qt[d0+u+3][r] = q4.w * 0.125f;
        }
    }

    float o[4][4];
    float m_i[4], l_i[4];
    #pragma unroll
    for (int i = 0; i < 4; i++) {
        m_i[i] = -1e30f; l_i[i] = 0.f;
        #pragma unroll
        for (int j = 0; j < 4; j++) o[i][j] = 0.f;
    }

    for (int kt = 0; kt <= qt; kt++) {
        __syncthreads();   // prior V reads done (and Q store visible on iter 0)
        // K tile, transposed [d][c], stride 64
        {
            const int c  = tid >> 2;
            const int d0 = (tid & 3) << 4;
            const float* krow = g_k + ((size_t)bh * SS + (size_t)kt * 64 + c) * DD + d0;
            #pragma unroll
            for (int u = 0; u < 16; u += 4) {
                float4 k4 = *(const float4*)(krow + u);
                KVs[(d0+u+0)*64 + c] = k4.x;
                KVs[(d0+u+1)*64 + c] = k4.y;
                KVs[(d0+u+2)*64 + c] = k4.z;
                KVs[(d0+u+3)*64 + c] = k4.w;
            }
        }
        __syncthreads();

        // scores: rows 4ty+i, key cols 4tx+j  (both operands float4)
        float sc[4][4];
        #pragma unroll
        for (int i = 0; i < 4; i++)
            #pragma unroll
            for (int j = 0; j < 4; j++) sc[i][j] = 0.f;

        #pragma unroll 8
        for (int d = 0; d < 64; d++) {
            const float4 q4 = *(const float4*)(&Qt[d][ty << 2]);
            const float4 k4 = *(const float4*)(&KVs[d*64 + (tx << 2)]);
            sc[0][0] += q4.x*k4.x; sc[0][1] += q4.x*k4.y; sc[0][2] += q4.x*k4.z; sc[0][3] += q4.x*k4.w;
            sc[1][0] += q4.y*k4.x; sc[1][1] += q4.y*k4.y; sc[1][2] += q4.y*k4.z; sc[1][3] += q4.y*k4.w;
            sc[2][0] += q4.z*k4.x; sc[2][1] += q4.z*k4.y; sc[2][2] += q4.z*k4.z; sc[2][3] += q4.z*k4.w;
            sc[3][0] += q4.w*k4.x; sc[3][1] += q4.w*k4.y; sc[3][2] += q4.w*k4.z; sc[3][3] += q4.w*k4.w;
        }

        // causal mask only on diagonal tile
        if (kt == qt) {
            #pragma unroll
            for (int i = 0; i < 4; i++) {
                const int qr = (ty << 2) + i;
                #pragma unroll
                for (int j = 0; j < 4; j++)
                    if ((tx << 2) + j > qr) sc[i][j] = -1e30f;
            }
        }

        // online softmax (state in registers, 16-lane shfl reductions)
        #pragma unroll
        for (int i = 0; i < 4; i++) {
            float mx = fmaxf(fmaxf(sc[i][0], sc[i][1]), fmaxf(sc[i][2], sc[i][3]));
            #pragma unroll
            for (int off = 8; off > 0; off >>= 1)
                mx = fmaxf(mx, __shfl_xor_sync(0xffffffffu, mx, off));
            const float mnew = fmaxf(m_i[i], mx);
            sc[i][0] = __expf(sc[i][0] - mnew);
            sc[i][1] = __expf(sc[i][1] - mnew);
            sc[i][2] = __expf(sc[i][2] - mnew);
            sc[i][3] = __expf(sc[i][3] - mnew);
            float rs = (sc[i][0] + sc[i][1]) + (sc[i][2] + sc[i][3]);
            #pragma unroll
            for (int off = 8; off > 0; off >>= 1)
                rs += __shfl_xor_sync(0xffffffffu, rs, off);
            const float al = __expf(m_i[i] - mnew);
            l_i[i] = l_i[i] * al + rs;
            m_i[i] = mnew;
            o[i][0] *= al; o[i][1] *= al; o[i][2] *= al; o[i][3] *= al;
        }

        // write P transposed with rotation swizzle: row c=4tx+j, col ((ty+tx)&15)*4
        {
            const int col0 = ((ty + tx) & 15) << 2;
            #pragma unroll
            for (int j = 0; j < 4; j++)
                *(float4*)(&Pst[(tx << 2) + j][col0]) =
                    make_float4(sc[0][j], sc[1][j], sc[2][j], sc[3][j]);
        }

        __syncthreads();  // P visible, K reads done -> safe to overwrite with V
        // V tile, row-major [c][d], stride 64
        {
            const int c  = tid >> 2;
            const int d0 = (tid & 3) << 4;
            const float* vrow = g_v + ((size_t)bh * SS + (size_t)kt * 64 + c) * DD + d0;
            #pragma unroll
            for (int u = 0; u < 16; u += 4)
                *(float4*)(&KVs[c*64 + d0 + u]) = *(const float4*)(vrow + u);
        }
        __syncthreads();

        // O += P @ V   (d cols 4tx+j)
        #pragma unroll 8
        for (int c = 0; c < 64; c++) {
            const int col = ((ty + (c >> 2)) & 15) << 2;
            const float4 pv = *(const float4*)(&Pst[c][col]);
            const float4 vv = *(const float4*)(&KVs[c*64 + (tx << 2)]);
            o[0][0] += pv.x*vv.x; o[0][1] += pv.x*vv.y; o[0][2] += pv.x*vv.z; o[0][3] += pv.x*vv.w;
            o[1][0] += pv.y*vv.x; o[1][1] += pv.y*vv.y; o[1][2] += pv.y*vv.z; o[1][3] += pv.y*vv.w;
            o[2][0] += pv.z*vv.x; o[2][1] += pv.z*vv.y; o[2][2] += pv.z*vv.z; o[2][3] += pv.z*vv.w;
            o[3][0] += pv.w*vv.x; o[3][1] += pv.w*vv.y; o[3][2] += pv.w*vv.z; o[3][3] += pv.w*vv.w;
        }
    }

    #pragma unroll
    for (int i = 0; i < 4; i++) {
        const float inv = 1.f / l_i[i];
        const int qr = qt*64 + (ty << 2) + i;
        float* yrow = g_y + ((size_t)b * SS + qr) * EE + h * DD + (tx << 2);
        *(float4*)yrow = make_float4(o[i][0]*inv, o[i][1]*inv, o[i][2]*inv, o[i][3]*inv);
    }
}

// ---------------- launch --------------------------------------------------
extern "C" void kernel_launch(void* const* d_in, const int* in_sizes, int n_in,
                              void* d_out, int out_size) {
    (void)in_sizes; (void)n_in; (void)out_size;
    const float* x    = (const float*)d_in[0];
    const float* Wqkv = (const float*)d_in[1];
    const float* Wo   = (const float*)d_in[2];
    float* out = (float*)d_out;

    rope_tables_kernel<<<(SS*32 + 255)/256, 256>>>();
    // x @ Wqkv^T -> g_qkv
    sgemm_nt<false, true><<<dim3(3*EE/128, MROWS/128), 256>>>(x, Wqkv, nullptr, MROWS, 3*EE, EE);
    rope_split_kernel<<<(BB*SS*HH*32)/256, 256>>>();
    flash_kernel<<<dim3(SS/64, BB*HH), 256>>>();
    // g_y @ Wo^T -> out
    sgemm_nt<true, false><<<dim3(EE/128, MROWS/128), 256>>>(nullptr, Wo, out, MROWS, EE, EE);
}

// round 8
// speedup vs baseline: 1.5851x; 1.5087x over previous
#include <cuda_runtime.h>
#include <math.h>
#include <stdint.h>

#define BB 2
#define SS 2048
#define EE 1024
#define HH 16
#define DD 64
#define MROWS (BB*SS)          // 4096

// ---- scratch (device globals: allocation-free rule) ----
__device__ float g_qkv[(size_t)MROWS * 3 * EE];      // 50.3 MB
__device__ float g_q[(size_t)BB * HH * SS * DD];     // 16.8 MB
__device__ float g_k[(size_t)BB * HH * SS * DD];
__device__ float g_v[(size_t)BB * HH * SS * DD];
__device__ float g_y[(size_t)MROWS * EE];
__device__ float g_cos[SS * (DD/2)];
__device__ float g_sin[SS * (DD/2)];

// ================= RoPE tables =============================================
__global__ void rope_tables_kernel() {
    int idx = blockIdx.x * blockDim.x + threadIdx.x;   // SS*32 threads
    if (idx >= SS * 32) return;
    int i = idx & 31;
    int s = idx >> 5;
    float theta = (float)exp(-2.0 * (double)i / 64.0 * log(10000.0));
    float freq  = (float)s * theta;
    double fr = (double)freq;
    g_cos[idx] = (float)cos(fr);
    g_sin[idx] = (float)sin(fr);
}

// ================= TF32 mma.sync GEMM (NT): C[m,n]=sum_k A[m,k]*B[n,k] =====
__device__ __forceinline__ uint32_t f2tf32(float x) {
    uint32_t r;
    asm("cvt.rna.tf32.f32 %0, %1;" : "=r"(r) : "f"(x));
    return r;
}
#define MMA_TF32(c, a, b) \
    asm volatile("mma.sync.aligned.m16n8k8.row.col.f32.tf32.tf32.f32 " \
                 "{%0,%1,%2,%3},{%4,%5,%6,%7},{%8,%9},{%0,%1,%2,%3};" \
                 : "+f"((c)[0]), "+f"((c)[1]), "+f"((c)[2]), "+f"((c)[3]) \
                 : "r"((a)[0]), "r"((a)[1]), "r"((a)[2]), "r"((a)[3]), \
                   "r"((b)[0]), "r"((b)[1]))

// CTA tile 128x128, 8 warps in 2(m) x 4(n), warp tile 64x32, K-chunk 16.
#define KC 16
#define SMS 20   // smem row stride (floats): conflict-free fragment gathers

template<bool A_FROM_Y, bool C_TO_QKV>
__global__ void __launch_bounds__(256, 2)
tf32_gemm(const float* __restrict__ Aparam, const float* __restrict__ Bparam,
          float* __restrict__ Cparam, int Nn, int Kk) {
    const float* A = A_FROM_Y ? (const float*)g_y : Aparam;
    const float* B = Bparam;
    float*       C = C_TO_QKV ? (float*)g_qkv : Cparam;

    __shared__ uint32_t As[128][SMS];
    __shared__ uint32_t Bs[128][SMS];

    const int tid = threadIdx.x;
    const int wid = tid >> 5;
    const int lane = tid & 31;
    const int grp = lane >> 2;          // 0..7
    const int tig = lane & 3;           // 0..3
    const int warp_m = (wid & 1) * 64;
    const int warp_n = (wid >> 1) * 32;
    const int bm = blockIdx.y * 128;
    const int bn = blockIdx.x * 128;

    // global-load assignment: thread covers float4 slots f = 2*tid + {0,1}
    const int r0g = (2*tid + 0) >> 2, c0g = ((2*tid + 0) & 3) * 4;
    const int r1g = (2*tid + 1) >> 2, c1g = ((2*tid + 1) & 3) * 4;

    float acc[4][4][4];
    #pragma unroll
    for (int i = 0; i < 4; i++)
        #pragma unroll
        for (int j = 0; j < 4; j++)
            #pragma unroll
            for (int e = 0; e < 4; e++) acc[i][j][e] = 0.f;

    float4 ra0, ra1, rb0, rb1;
    // prefetch chunk 0
    ra0 = *(const float4*)(A + (size_t)(bm + r0g) * Kk + c0g);
    ra1 = *(const float4*)(A + (size_t)(bm + r1g) * Kk + c1g);
    rb0 = *(const float4*)(B + (size_t)(bn + r0g) * Kk + c0g);
    rb1 = *(const float4*)(B + (size_t)(bn + r1g) * Kk + c1g);

    const int NC = Kk / KC;
    for (int kc = 0; kc < NC; kc++) {
        __syncthreads();   // previous chunk's smem reads complete
        As[r0g][c0g+0] = f2tf32(ra0.x); As[r0g][c0g+1] = f2tf32(ra0.y);
        As[r0g][c0g+2] = f2tf32(ra0.z); As[r0g][c0g+3] = f2tf32(ra0.w);
        As[r1g][c1g+0] = f2tf32(ra1.x); As[r1g][c1g+1] = f2tf32(ra1.y);
        As[r1g][c1g+2] = f2tf32(ra1.z); As[r1g][c1g+3] = f2tf32(ra1.w);
        Bs[r0g][c0g+0] = f2tf32(rb0.x); Bs[r0g][c0g+1] = f2tf32(rb0.y);
        Bs[r0g][c0g+2] = f2tf32(rb0.z); Bs[r0g][c0g+3] = f2tf32(rb0.w);
        Bs[r1g][c1g+0] = f2tf32(rb1.x); Bs[r1g][c1g+1] = f2tf32(rb1.y);
        Bs[r1g][c1g+2] = f2tf32(rb1.z); Bs[r1g][c1g+3] = f2tf32(rb1.w);
        __syncthreads();

        if (kc + 1 < NC) {
            const int kb = (kc + 1) * KC;
            ra0 = *(const float4*)(A + (size_t)(bm + r0g) * Kk + kb + c0g);
            ra1 = *(const float4*)(A + (size_t)(bm + r1g) * Kk + kb + c1g);
            rb0 = *(const float4*)(B + (size_t)(bn + r0g) * Kk + kb + c0g);
            rb1 = *(const float4*)(B + (size_t)(bn + r1g) * Kk + kb + c1g);
        }

        #pragma unroll
        for (int ks = 0; ks < 2; ks++) {
            const int k0 = ks * 8;
            uint32_t af[4][4], bf[4][2];
            #pragma unroll
            for (int i = 0; i < 4; i++) {
                const int r = warp_m + 16*i + grp;
                af[i][0] = As[r    ][k0 + tig];
                af[i][1] = As[r + 8][k0 + tig];
                af[i][2] = As[r    ][k0 + tig + 4];
                af[i][3] = As[r + 8][k0 + tig + 4];
            }
            #pragma unroll
            for (int j = 0; j < 4; j++) {
                const int n0 = warp_n + 8*j + grp;
                bf[j][0] = Bs[n0][k0 + tig];
                bf[j][1] = Bs[n0][k0 + tig + 4];
            }
            #pragma unroll
            for (int i = 0; i < 4; i++)
                #pragma unroll
                for (int j = 0; j < 4; j++)
                    MMA_TF32(acc[i][j], af[i], bf[j]);
        }
    }

    // epilogue: c0,c1 at (row grp, cols 2tig,2tig+1), c2,c3 at row grp+8
    #pragma unroll
    for (int i = 0; i < 4; i++) {
        const int r0 = bm + warp_m + 16*i + grp;
        #pragma unroll
        for (int j = 0; j < 4; j++) {
            const int cn = bn + warp_n + 8*j + 2*tig;
            *(float2*)(C + (size_t)r0 * Nn + cn)       = make_float2(acc[i][j][0], acc[i][j][1]);
            *(float2*)(C + (size_t)(r0 + 8) * Nn + cn) = make_float2(acc[i][j][2], acc[i][j][3]);
        }
    }
}

// ================= RoPE apply + split qkv -> q,k,v [B,H,S,D] ===============
__global__ void rope_split_kernel() {
    int idx = blockIdx.x * 256 + threadIdx.x;   // BB*SS*HH*32 total
    const int i = idx & 31;
    const int h = (idx >> 5) & 15;
    const int s = (idx >> 9) & (SS - 1);
    const int b = idx >> 20;
    const float c  = g_cos[(s << 5) + i];
    const float sn = g_sin[(s << 5) + i];
    const float* row = g_qkv + (size_t)(b * SS + s) * (3 * EE);
    const float2 qp = ((const float2*)(row          ))[(h << 5) + i];
    const float2 kp = ((const float2*)(row +     EE))[(h << 5) + i];
    const float2 vp = ((const float2*)(row + 2 * EE))[(h << 5) + i];
    const size_t base2 = (size_t)((b * HH + h) * SS + s) * 32 + i;
    ((float2*)g_q)[base2] = make_float2(qp.x * c - qp.y * sn, qp.x * sn + qp.y * c);
    ((float2*)g_k)[base2] = make_float2(kp.x * c - kp.y * sn, kp.x * sn + kp.y * c);
    ((float2*)g_v)[base2] = vp;
}

// ================= causal flash attention, fp32, Bq=64 Bk=64 ===============
__global__ void __launch_bounds__(256)
flash_kernel() {
    const int qt = (int)gridDim.x - 1 - (int)blockIdx.x;  // big tiles first
    const int bh = blockIdx.y;
    const int b = bh >> 4;
    const int h = bh & 15;
    const int tid = threadIdx.x;
    const int tx = tid & 15;
    const int ty = tid >> 4;

    __shared__ float Qt[64][64];      // [d][r]  (transposed, pre-scaled)
    __shared__ float KVs[64*64];      // K: [d][c]; then V: [c][d]
    __shared__ float Pst[64][64];     // [c][rot-swizzled r]

    {
        const int r  = tid >> 2;
        const int d0 = (tid & 3) << 4;
        const float* qrow = g_q + ((size_t)bh * SS + (size_t)qt * 64 + r) * DD + d0;
        #pragma unroll
        for (int u = 0; u < 16; u += 4) {
            float4 q4 = *(const float4*)(qrow + u);
            Qt[d0+u+0][r] = q4.x * 0.125f; Qt[d0+u+1][r] = q4.y * 0.125f;
            Qt[d0+u+2][r] = q4.z * 0.125f; Qt[d0+u+3][r] = q4.w * 0.125f;
        }
    }

    float o[4][4];
    float m_i[4], l_i[4];
    #pragma unroll
    for (int i = 0; i < 4; i++) {
        m_i[i] = -1e30f; l_i[i] = 0.f;
        #pragma unroll
        for (int j = 0; j < 4; j++) o[i][j] = 0.f;
    }

    for (int kt = 0; kt <= qt; kt++) {
        __syncthreads();
        {
            const int c  = tid >> 2;
            const int d0 = (tid & 3) << 4;
            const float* krow = g_k + ((size_t)bh * SS + (size_t)kt * 64 + c) * DD + d0;
            #pragma unroll
            for (int u = 0; u < 16; u += 4) {
                float4 k4 = *(const float4*)(krow + u);
                KVs[(d0+u+0)*64 + c] = k4.x;
                KVs[(d0+u+1)*64 + c] = k4.y;
                KVs[(d0+u+2)*64 + c] = k4.z;
                KVs[(d0+u+3)*64 + c] = k4.w;
            }
        }
        __syncthreads();

        float sc[4][4];
        #pragma unroll
        for (int i = 0; i < 4; i++)
            #pragma unroll
            for (int j = 0; j < 4; j++) sc[i][j] = 0.f;

        #pragma unroll 8
        for (int d = 0; d < 64; d++) {
            const float4 q4 = *(const float4*)(&Qt[d][ty << 2]);
            const float4 k4 = *(const float4*)(&KVs[d*64 + (tx << 2)]);
            sc[0][0] += q4.x*k4.x; sc[0][1] += q4.x*k4.y; sc[0][2] += q4.x*k4.z; sc[0][3] += q4.x*k4.w;
            sc[1][0] += q4.y*k4.x; sc[1][1] += q4.y*k4.y; sc[1][2] += q4.y*k4.z; sc[1][3] += q4.y*k4.w;
            sc[2][0] += q4.z*k4.x; sc[2][1] += q4.z*k4.y; sc[2][2] += q4.z*k4.z; sc[2][3] += q4.z*k4.w;
            sc[3][0] += q4.w*k4.x; sc[3][1] += q4.w*k4.y; sc[3][2] += q4.w*k4.z; sc[3][3] += q4.w*k4.w;
        }

        if (kt == qt) {
            #pragma unroll
            for (int i = 0; i < 4; i++) {
                const int qr = (ty << 2) + i;
                #pragma unroll
                for (int j = 0; j < 4; j++)
                    if ((tx << 2) + j > qr) sc[i][j] = -1e30f;
            }
        }

        #pragma unroll
        for (int i = 0; i < 4; i++) {
            float mx = fmaxf(fmaxf(sc[i][0], sc[i][1]), fmaxf(sc[i][2], sc[i][3]));
            #pragma unroll
            for (int off = 8; off > 0; off >>= 1)
                mx = fmaxf(mx, __shfl_xor_sync(0xffffffffu, mx, off));
            const float mnew = fmaxf(m_i[i], mx);
            sc[i][0] = __expf(sc[i][0] - mnew);
            sc[i][1] = __expf(sc[i][1] - mnew);
            sc[i][2] = __expf(sc[i][2] - mnew);
            sc[i][3] = __expf(sc[i][3] - mnew);
            float rs = (sc[i][0] + sc[i][1]) + (sc[i][2] + sc[i][3]);
            #pragma unroll
            for (int off = 8; off > 0; off >>= 1)
                rs += __shfl_xor_sync(0xffffffffu, rs, off);
            const float al = __expf(m_i[i] - mnew);
            l_i[i] = l_i[i] * al + rs;
            m_i[i] = mnew;
            o[i][0] *= al; o[i][1] *= al; o[i][2] *= al; o[i][3] *= al;
        }

        {
            const int col0 = ((ty + tx) & 15) << 2;
            #pragma unroll
            for (int j = 0; j < 4; j++)
                *(float4*)(&Pst[(tx << 2) + j][col0]) =
                    make_float4(sc[0][j], sc[1][j], sc[2][j], sc[3][j]);
        }

        __syncthreads();
        {
            const int c  = tid >> 2;
            const int d0 = (tid & 3) << 4;
            const float* vrow = g_v + ((size_t)bh * SS + (size_t)kt * 64 + c) * DD + d0;
            #pragma unroll
            for (int u = 0; u < 16; u += 4)
                *(float4*)(&KVs[c*64 + d0 + u]) = *(const float4*)(vrow + u);
        }
        __syncthreads();

        #pragma unroll 8
        for (int c = 0; c < 64; c++) {
            const int col = ((ty + (c >> 2)) & 15) << 2;
            const float4 pv = *(const float4*)(&Pst[c][col]);
            const float4 vv = *(const float4*)(&KVs[c*64 + (tx << 2)]);
            o[0][0] += pv.x*vv.x; o[0][1] += pv.x*vv.y; o[0][2] += pv.x*vv.z; o[0][3] += pv.x*vv.w;
            o[1][0] += pv.y*vv.x; o[1][1] += pv.y*vv.y; o[1][2] += pv.y*vv.z; o[1][3] += pv.y*vv.w;
            o[2][0] += pv.z*vv.x; o[2][1] += pv.z*vv.y; o[2][2] += pv.z*vv.z; o[2][3] += pv.z*vv.w;
            o[3][0] += pv.w*vv.x; o[3][1] += pv.w*vv.y; o[3][2] += pv.w*vv.z; o[3][3] += pv.w*vv.w;
        }
    }

    #pragma unroll
    for (int i = 0; i < 4; i++) {
        const float inv = 1.f / l_i[i];
        const int qr = qt*64 + (ty << 2) + i;
        float* yrow = g_y + ((size_t)b * SS + qr) * EE + h * DD + (tx << 2);
        *(float4*)yrow = make_float4(o[i][0]*inv, o[i][1]*inv, o[i][2]*inv, o[i][3]*inv);
    }
}

// ================= launch ==================================================
extern "C" void kernel_launch(void* const* d_in, const int* in_sizes, int n_in,
                              void* d_out, int out_size) {
    (void)in_sizes; (void)n_in; (void)out_size;
    const float* x    = (const float*)d_in[0];
    const float* Wqkv = (const float*)d_in[1];
    const float* Wo   = (const float*)d_in[2];
    float* out = (float*)d_out;

    rope_tables_kernel<<<(SS*32 + 255)/256, 256>>>();
    // x @ Wqkv^T -> g_qkv   (M=4096, N=3072, K=1024)
    tf32_gemm<false, true><<<dim3(3*EE/128, MROWS/128), 256>>>(x, Wqkv, nullptr, 3*EE, EE);
    rope_split_kernel<<<(BB*SS*HH*32)/256, 256>>>();
    flash_kernel<<<dim3(SS/64, BB*HH), 256>>>();
    // g_y @ Wo^T -> out     (M=4096, N=1024, K=1024)
    tf32_gemm<true, false><<<dim3(EE/128, MROWS/128), 256>>>(nullptr, Wo, out, EE, EE);
}

// round 9
// speedup vs baseline: 2.6640x; 1.6806x over previous
#include <cuda_runtime.h>
#include <math.h>
#include <stdint.h>

#define BB 2
#define SS 2048
#define EE 1024
#define HH 16
#define DD 64
#define MROWS (BB*SS)          // 4096

// ---- scratch (device globals: allocation-free rule) ----
__device__ float g_qkv[(size_t)MROWS * 3 * EE];      // 50.3 MB
__device__ float g_q[(size_t)BB * HH * SS * DD];     // 16.8 MB
__device__ float g_k[(size_t)BB * HH * SS * DD];
__device__ float g_v[(size_t)BB * HH * SS * DD];
__device__ float g_y[(size_t)MROWS * EE];
__device__ float g_cos[SS * (DD/2)];
__device__ float g_sin[SS * (DD/2)];

// ================= RoPE tables =============================================
__global__ void rope_tables_kernel() {
    int idx = blockIdx.x * blockDim.x + threadIdx.x;   // SS*32 threads
    if (idx >= SS * 32) return;
    int i = idx & 31;
    int s = idx >> 5;
    float theta = (float)exp(-2.0 * (double)i / 64.0 * log(10000.0));
    float freq  = (float)s * theta;
    double fr = (double)freq;
    g_cos[idx] = (float)cos(fr);
    g_sin[idx] = (float)sin(fr);
}

// ================= common TF32 helpers =====================================
__device__ __forceinline__ uint32_t f2tf32(float x) {
    uint32_t r;
    asm("cvt.rna.tf32.f32 %0, %1;" : "=r"(r) : "f"(x));
    return r;
}
#define MMA_TF32(c, a, b) \
    asm volatile("mma.sync.aligned.m16n8k8.row.col.f32.tf32.tf32.f32 " \
                 "{%0,%1,%2,%3},{%4,%5,%6,%7},{%8,%9},{%0,%1,%2,%3};" \
                 : "+f"((c)[0]), "+f"((c)[1]), "+f"((c)[2]), "+f"((c)[3]) \
                 : "r"((a)[0]), "r"((a)[1]), "r"((a)[2]), "r"((a)[3]), \
                   "r"((b)[0]), "r"((b)[1]))

// ================= TF32 mma.sync GEMM (NT): C[m,n]=sum_k A[m,k]*B[n,k] =====
// CTA tile 128x128, 8 warps in 2(m) x 4(n), warp tile 64x32, K-chunk 16.
#define KC 16
#define SMS 20   // smem row stride (floats): conflict-free fragment gathers

template<bool A_FROM_Y, bool C_TO_QKV>
__global__ void __launch_bounds__(256, 2)
tf32_gemm(const float* __restrict__ Aparam, const float* __restrict__ Bparam,
          float* __restrict__ Cparam, int Nn, int Kk) {
    const float* A = A_FROM_Y ? (const float*)g_y : Aparam;
    const float* B = Bparam;
    float*       C = C_TO_QKV ? (float*)g_qkv : Cparam;

    __shared__ uint32_t As[128][SMS];
    __shared__ uint32_t Bs[128][SMS];

    const int tid = threadIdx.x;
    const int wid = tid >> 5;
    const int lane = tid & 31;
    const int grp = lane >> 2;          // 0..7
    const int tig = lane & 3;           // 0..3
    const int warp_m = (wid & 1) * 64;
    const int warp_n = (wid >> 1) * 32;
    const int bm = blockIdx.y * 128;
    const int bn = blockIdx.x * 128;

    const int r0g = (2*tid + 0) >> 2, c0g = ((2*tid + 0) & 3) * 4;
    const int r1g = (2*tid + 1) >> 2, c1g = ((2*tid + 1) & 3) * 4;

    float acc[4][4][4];
    #pragma unroll
    for (int i = 0; i < 4; i++)
        #pragma unroll
        for (int j = 0; j < 4; j++)
            #pragma unroll
            for (int e = 0; e < 4; e++) acc[i][j][e] = 0.f;

    float4 ra0, ra1, rb0, rb1;
    ra0 = *(const float4*)(A + (size_t)(bm + r0g) * Kk + c0g);
    ra1 = *(const float4*)(A + (size_t)(bm + r1g) * Kk + c1g);
    rb0 = *(const float4*)(B + (size_t)(bn + r0g) * Kk + c0g);
    rb1 = *(const float4*)(B + (size_t)(bn + r1g) * Kk + c1g);

    const int NC = Kk / KC;
    for (int kc = 0; kc < NC; kc++) {
        __syncthreads();
        As[r0g][c0g+0] = f2tf32(ra0.x); As[r0g][c0g+1] = f2tf32(ra0.y);
        As[r0g][c0g+2] = f2tf32(ra0.z); As[r0g][c0g+3] = f2tf32(ra0.w);
        As[r1g][c1g+0] = f2tf32(ra1.x); As[r1g][c1g+1] = f2tf32(ra1.y);
        As[r1g][c1g+2] = f2tf32(ra1.z); As[r1g][c1g+3] = f2tf32(ra1.w);
        Bs[r0g][c0g+0] = f2tf32(rb0.x); Bs[r0g][c0g+1] = f2tf32(rb0.y);
        Bs[r0g][c0g+2] = f2tf32(rb0.z); Bs[r0g][c0g+3] = f2tf32(rb0.w);
        Bs[r1g][c1g+0] = f2tf32(rb1.x); Bs[r1g][c1g+1] = f2tf32(rb1.y);
        Bs[r1g][c1g+2] = f2tf32(rb1.z); Bs[r1g][c1g+3] = f2tf32(rb1.w);
        __syncthreads();

        if (kc + 1 < NC) {
            const int kb = (kc + 1) * KC;
            ra0 = *(const float4*)(A + (size_t)(bm + r0g) * Kk + kb + c0g);
            ra1 = *(const float4*)(A + (size_t)(bm + r1g) * Kk + kb + c1g);
            rb0 = *(const float4*)(B + (size_t)(bn + r0g) * Kk + kb + c0g);
            rb1 = *(const float4*)(B + (size_t)(bn + r1g) * Kk + kb + c1g);
        }

        #pragma unroll
        for (int ks = 0; ks < 2; ks++) {
            const int k0 = ks * 8;
            uint32_t af[4][4], bf[4][2];
            #pragma unroll
            for (int i = 0; i < 4; i++) {
                const int r = warp_m + 16*i + grp;
                af[i][0] = As[r    ][k0 + tig];
                af[i][1] = As[r + 8][k0 + tig];
                af[i][2] = As[r    ][k0 + tig + 4];
                af[i][3] = As[r + 8][k0 + tig + 4];
            }
            #pragma unroll
            for (int j = 0; j < 4; j++) {
                const int n0 = warp_n + 8*j + grp;
                bf[j][0] = Bs[n0][k0 + tig];
                bf[j][1] = Bs[n0][k0 + tig + 4];
            }
            #pragma unroll
            for (int i = 0; i < 4; i++)
                #pragma unroll
                for (int j = 0; j < 4; j++)
                    MMA_TF32(acc[i][j], af[i], bf[j]);
        }
    }

    #pragma unroll
    for (int i = 0; i < 4; i++) {
        const int r0 = bm + warp_m + 16*i + grp;
        #pragma unroll
        for (int j = 0; j < 4; j++) {
            const int cn = bn + warp_n + 8*j + 2*tig;
            *(float2*)(C + (size_t)r0 * Nn + cn)       = make_float2(acc[i][j][0], acc[i][j][1]);
            *(float2*)(C + (size_t)(r0 + 8) * Nn + cn) = make_float2(acc[i][j][2], acc[i][j][3]);
        }
    }
}

// ================= RoPE apply + split qkv -> q,k,v [B,H,S,D] ===============
__global__ void rope_split_kernel() {
    int idx = blockIdx.x * 256 + threadIdx.x;   // BB*SS*HH*32 total
    const int i = idx & 31;
    const int h = (idx >> 5) & 15;
    const int s = (idx >> 9) & (SS - 1);
    const int b = idx >> 20;
    const float c  = g_cos[(s << 5) + i];
    const float sn = g_sin[(s << 5) + i];
    const float* row = g_qkv + (size_t)(b * SS + s) * (3 * EE);
    const float2 qp = ((const float2*)(row          ))[(h << 5) + i];
    const float2 kp = ((const float2*)(row +     EE))[(h << 5) + i];
    const float2 vp = ((const float2*)(row + 2 * EE))[(h << 5) + i];
    const size_t base2 = (size_t)((b * HH + h) * SS + s) * 32 + i;
    ((float2*)g_q)[base2] = make_float2(qp.x * c - qp.y * sn, qp.x * sn + qp.y * c);
    ((float2*)g_k)[base2] = make_float2(kp.x * c - kp.y * sn, kp.x * sn + kp.y * c);
    ((float2*)g_v)[base2] = vp;
}

// ================= TF32 tensor-core causal flash, Bq=128 Bk=64 =============
// 8 warps; warp w owns q-rows 128*tq + 16w .. +15 (m16), full n=64 keys/dims.
// S/P acc layout (m16n8): thread(grp,tig) rows {grp,grp+8}, cols {2tig,2tig+1}.
#define FKS 68   // K/V smem row stride (uint32): conflict-free fragment banks

__global__ void __launch_bounds__(256, 2)
flash_tc_kernel() {
    const int tq = (int)gridDim.x - 1 - (int)blockIdx.x;  // big tiles first
    const int bh = blockIdx.y;
    const int b = bh >> 4, h = bh & 15;
    const int tid = threadIdx.x;
    const int wid = tid >> 5;
    const int lane = tid & 31;
    const int grp = lane >> 2;          // 0..7
    const int tig = lane & 3;           // 0..3

    __shared__ __align__(16) uint32_t Ksm[64][FKS];
    __shared__ __align__(16) uint32_t Vsm[64][FKS];

    // ---- Q fragments in registers (scaled by 1/8, tf32) ----
    uint32_t qf[8][4];
    {
        const float* q0 = g_q + ((size_t)bh * SS + 128*tq + 16*wid) * DD;
        #pragma unroll
        for (int kg = 0; kg < 8; kg++) {
            qf[kg][0] = f2tf32(q0[(size_t)grp * DD       + 8*kg + tig    ] * 0.125f);
            qf[kg][1] = f2tf32(q0[(size_t)(grp+8) * DD   + 8*kg + tig    ] * 0.125f);
            qf[kg][2] = f2tf32(q0[(size_t)grp * DD       + 8*kg + tig + 4] * 0.125f);
            qf[kg][3] = f2tf32(q0[(size_t)(grp+8) * DD   + 8*kg + tig + 4] * 0.125f);
        }
    }

    float o[8][4];
    #pragma unroll
    for (int j = 0; j < 8; j++)
        #pragma unroll
        for (int e = 0; e < 4; e++) o[j][e] = 0.f;
    float m0 = -1e30f, m1 = -1e30f, l0 = 0.f, l1 = 0.f;

    const int qrow0 = 128*tq + 16*wid + grp;
    const int qrow1 = qrow0 + 8;

    const int nkt = 2*tq + 2;
    for (int kt = 0; kt < nkt; kt++) {
        __syncthreads();   // prior PV reads of Vsm complete
        // ---- load K and V tiles (64x64) as tf32 ----
        {
            const float* kb = g_k + ((size_t)bh * SS + (size_t)64*kt) * DD;
            const float* vb = g_v + ((size_t)bh * SS + (size_t)64*kt) * DD;
            #pragma unroll
            for (int i = 0; i < 4; i++) {
                const int f = i*256 + tid;
                const int r = f >> 4;
                const int c = (f & 15) << 2;
                const float4 k4 = *(const float4*)(kb + (size_t)r * DD + c);
                const float4 v4 = *(const float4*)(vb + (size_t)r * DD + c);
                uint4 ku = make_uint4(f2tf32(k4.x), f2tf32(k4.y), f2tf32(k4.z), f2tf32(k4.w));
                uint4 vu = make_uint4(f2tf32(v4.x), f2tf32(v4.y), f2tf32(v4.z), f2tf32(v4.w));
                *(uint4*)(&Ksm[r][c]) = ku;
                *(uint4*)(&Vsm[r][c]) = vu;
            }
        }
        __syncthreads();

        // ---- S = Q K^T  (64 MMAs: 8 k-groups x 8 n-frags) ----
        float s[8][4];
        #pragma unroll
        for (int j = 0; j < 8; j++)
            #pragma unroll
            for (int e = 0; e < 4; e++) s[j][e] = 0.f;

        #pragma unroll
        for (int kg = 0; kg < 8; kg++) {
            const int k0 = 8*kg;
            #pragma unroll
            for (int j = 0; j < 8; j++) {
                uint32_t bfr[2];
                bfr[0] = Ksm[8*j + grp][k0 + tig];
                bfr[1] = Ksm[8*j + grp][k0 + tig + 4];
                MMA_TF32(s[j], qf[kg], bfr);
            }
        }

        // ---- causal mask (only last two k-tiles can touch the diagonal) ----
        if (kt >= 2*tq) {
            #pragma unroll
            for (int j = 0; j < 8; j++) {
                const int kc = 64*kt + 8*j + 2*tig;
                if (kc     > qrow0) s[j][0] = -1e30f;
                if (kc + 1 > qrow0) s[j][1] = -1e30f;
                if (kc     > qrow1) s[j][2] = -1e30f;
                if (kc + 1 > qrow1) s[j][3] = -1e30f;
            }
        }

        // ---- online softmax (rows grp / grp+8; quad shfl reductions) ----
        float mx0 = -1e30f, mx1 = -1e30f;
        #pragma unroll
        for (int j = 0; j < 8; j++) {
            mx0 = fmaxf(mx0, fmaxf(s[j][0], s[j][1]));
            mx1 = fmaxf(mx1, fmaxf(s[j][2], s[j][3]));
        }
        mx0 = fmaxf(mx0, __shfl_xor_sync(0xffffffffu, mx0, 1));
        mx0 = fmaxf(mx0, __shfl_xor_sync(0xffffffffu, mx0, 2));
        mx1 = fmaxf(mx1, __shfl_xor_sync(0xffffffffu, mx1, 1));
        mx1 = fmaxf(mx1, __shfl_xor_sync(0xffffffffu, mx1, 2));
        const float mn0 = fmaxf(m0, mx0);
        const float mn1 = fmaxf(m1, mx1);
        const float a0 = __expf(m0 - mn0);
        const float a1 = __expf(m1 - mn1);
        m0 = mn0; m1 = mn1;

        float rs0 = 0.f, rs1 = 0.f;
        #pragma unroll
        for (int j = 0; j < 8; j++) {
            s[j][0] = __expf(s[j][0] - mn0);
            s[j][1] = __expf(s[j][1] - mn0);
            s[j][2] = __expf(s[j][2] - mn1);
            s[j][3] = __expf(s[j][3] - mn1);
            rs0 += s[j][0] + s[j][1];
            rs1 += s[j][2] + s[j][3];
        }
        rs0 += __shfl_xor_sync(0xffffffffu, rs0, 1);
        rs0 += __shfl_xor_sync(0xffffffffu, rs0, 2);
        rs1 += __shfl_xor_sync(0xffffffffu, rs1, 1);
        rs1 += __shfl_xor_sync(0xffffffffu, rs1, 2);
        l0 = l0 * a0 + rs0;
        l1 = l1 * a1 + rs1;

        #pragma unroll
        for (int j = 0; j < 8; j++) {
            o[j][0] *= a0; o[j][1] *= a0;
            o[j][2] *= a1; o[j][3] *= a1;
        }

        // ---- O += P V  (register shfl relayout of P into A-fragments) ----
        const int base4 = grp << 2;
        const int src1 = base4 + (tig >> 1);
        const int src2 = src1 + 2;
        const bool oddt = (tig & 1);
        #pragma unroll
        for (int kg = 0; kg < 8; kg++) {
            const float s1c0 = __shfl_sync(0xffffffffu, s[kg][0], src1);
            const float s1c1 = __shfl_sync(0xffffffffu, s[kg][1], src1);
            const float s1c2 = __shfl_sync(0xffffffffu, s[kg][2], src1);
            const float s1c3 = __shfl_sync(0xffffffffu, s[kg][3], src1);
            const float s2c0 = __shfl_sync(0xffffffffu, s[kg][0], src2);
            const float s2c1 = __shfl_sync(0xffffffffu, s[kg][1], src2);
            const float s2c2 = __shfl_sync(0xffffffffu, s[kg][2], src2);
            const float s2c3 = __shfl_sync(0xffffffffu, s[kg][3], src2);
            uint32_t af[4];
            af[0] = f2tf32(oddt ? s1c1 : s1c0);
            af[1] = f2tf32(oddt ? s1c3 : s1c2);
            af[2] = f2tf32(oddt ? s2c1 : s2c0);
            af[3] = f2tf32(oddt ? s2c3 : s2c2);
            const int k0 = 8*kg;
            #pragma unroll
            for (int j = 0; j < 8; j++) {
                uint32_t bfr[2];
                bfr[0] = Vsm[k0 + tig    ][8*j + grp];
                bfr[1] = Vsm[k0 + tig + 4][8*j + grp];
                MMA_TF32(o[j], af, bfr);
            }
        }
    }

    // ---- epilogue: normalize and write head slice of g_y ----
    const float inv0 = 1.f / l0;
    const float inv1 = 1.f / l1;
    float* y0 = g_y + ((size_t)b * SS + qrow0) * EE + h * DD;
    float* y1 = g_y + ((size_t)b * SS + qrow1) * EE + h * DD;
    #pragma unroll
    for (int j = 0; j < 8; j++) {
        const int cn = 8*j + 2*tig;
        *(float2*)(y0 + cn) = make_float2(o[j][0]*inv0, o[j][1]*inv0);
        *(float2*)(y1 + cn) = make_float2(o[j][2]*inv1, o[j][3]*inv1);
    }
}

// ================= launch ==================================================
extern "C" void kernel_launch(void* const* d_in, const int* in_sizes, int n_in,
                              void* d_out, int out_size) {
    (void)in_sizes; (void)n_in; (void)out_size;
    const float* x    = (const float*)d_in[0];
    const float* Wqkv = (const float*)d_in[1];
    const float* Wo   = (const float*)d_in[2];
    float* out = (float*)d_out;

    rope_tables_kernel<<<(SS*32 + 255)/256, 256>>>();
    // x @ Wqkv^T -> g_qkv   (M=4096, N=3072, K=1024)
    tf32_gemm<false, true><<<dim3(3*EE/128, MROWS/128), 256>>>(x, Wqkv, nullptr, 3*EE, EE);
    rope_split_kernel<<<(BB*SS*HH*32)/256, 256>>>();
    flash_tc_kernel<<<dim3(SS/128, BB*HH), 256>>>();
    // g_y @ Wo^T -> out     (M=4096, N=1024, K=1024)
    tf32_gemm<true, false><<<dim3(EE/128, MROWS/128), 256>>>(nullptr, Wo, out, EE, EE);
}

// round 10
// speedup vs baseline: 2.7056x; 1.0156x over previous
#include <cuda_runtime.h>
#include <math.h>
#include <stdint.h>

#define BB 2
#define SS 2048
#define EE 1024
#define HH 16
#define DD 64
#define MROWS (BB*SS)          // 4096

// ---- scratch (device globals: allocation-free rule) ----
__device__ float g_qkv[(size_t)MROWS * 3 * EE];      // 50.3 MB
__device__ float g_q[(size_t)BB * HH * SS * DD];     // 16.8 MB
__device__ float g_k[(size_t)BB * HH * SS * DD];
__device__ float g_v[(size_t)BB * HH * SS * DD];
__device__ float g_y[(size_t)MROWS * EE];
__device__ float g_cos[SS * (DD/2)];
__device__ float g_sin[SS * (DD/2)];

// ================= RoPE tables =============================================
__global__ void rope_tables_kernel() {
    int idx = blockIdx.x * blockDim.x + threadIdx.x;   // SS*32 threads
    if (idx >= SS * 32) return;
    int i = idx & 31;
    int s = idx >> 5;
    float theta = (float)exp(-2.0 * (double)i / 64.0 * log(10000.0));
    float freq  = (float)s * theta;
    double fr = (double)freq;
    g_cos[idx] = (float)cos(fr);
    g_sin[idx] = (float)sin(fr);
}

// ================= common TF32 helpers =====================================
__device__ __forceinline__ uint32_t f2tf32(float x) {
    uint32_t r;
    asm("cvt.rna.tf32.f32 %0, %1;" : "=r"(r) : "f"(x));
    return r;
}
#define MMA_TF32(c, a, b) \
    asm volatile("mma.sync.aligned.m16n8k8.row.col.f32.tf32.tf32.f32 " \
                 "{%0,%1,%2,%3},{%4,%5,%6,%7},{%8,%9},{%0,%1,%2,%3};" \
                 : "+f"((c)[0]), "+f"((c)[1]), "+f"((c)[2]), "+f"((c)[3]) \
                 : "r"((a)[0]), "r"((a)[1]), "r"((a)[2]), "r"((a)[3]), \
                   "r"((b)[0]), "r"((b)[1]))

// ================= TF32 mma.sync GEMM (NT): C[m,n]=sum_k A[m,k]*B[n,k] =====
// CTA tile 128x128, 8 warps in 2(m) x 4(n), warp tile 64x32, K-chunk 16.
// Double-buffered smem stages; register prefetch 2 chunks ahead; 1 sync/chunk.
#define KC 16
#define SMS 20   // smem row stride (floats): conflict-free fragment gathers

template<bool A_FROM_Y, bool C_TO_QKV>
__global__ void __launch_bounds__(256, 2)
tf32_gemm(const float* __restrict__ Aparam, const float* __restrict__ Bparam,
          float* __restrict__ Cparam, int Nn, int Kk) {
    const float* A = A_FROM_Y ? (const float*)g_y : Aparam;
    const float* B = Bparam;
    float*       C = C_TO_QKV ? (float*)g_qkv : Cparam;

    __shared__ uint32_t As[2][128][SMS];
    __shared__ uint32_t Bs[2][128][SMS];

    const int tid = threadIdx.x;
    const int wid = tid >> 5;
    const int lane = tid & 31;
    const int grp = lane >> 2;          // 0..7
    const int tig = lane & 3;           // 0..3
    const int warp_m = (wid & 1) * 64;
    const int warp_n = (wid >> 1) * 32;
    const int bm = blockIdx.y * 128;
    const int bn = blockIdx.x * 128;

    const int r0g = (2*tid + 0) >> 2, c0g = ((2*tid + 0) & 3) * 4;
    const int r1g = (2*tid + 1) >> 2, c1g = ((2*tid + 1) & 3) * 4;
    const float* Ap0 = A + (size_t)(bm + r0g) * Kk + c0g;
    const float* Ap1 = A + (size_t)(bm + r1g) * Kk + c1g;
    const float* Bp0 = B + (size_t)(bn + r0g) * Kk + c0g;
    const float* Bp1 = B + (size_t)(bn + r1g) * Kk + c1g;

    float acc[4][4][4];
    #pragma unroll
    for (int i = 0; i < 4; i++)
        #pragma unroll
        for (int j = 0; j < 4; j++)
            #pragma unroll
            for (int e = 0; e < 4; e++) acc[i][j][e] = 0.f;

    float4 ra0, ra1, rb0, rb1;

    // chunk 0 -> stage 0
    ra0 = *(const float4*)(Ap0);  ra1 = *(const float4*)(Ap1);
    rb0 = *(const float4*)(Bp0);  rb1 = *(const float4*)(Bp1);
    As[0][r0g][c0g+0] = f2tf32(ra0.x); As[0][r0g][c0g+1] = f2tf32(ra0.y);
    As[0][r0g][c0g+2] = f2tf32(ra0.z); As[0][r0g][c0g+3] = f2tf32(ra0.w);
    As[0][r1g][c1g+0] = f2tf32(ra1.x); As[0][r1g][c1g+1] = f2tf32(ra1.y);
    As[0][r1g][c1g+2] = f2tf32(ra1.z); As[0][r1g][c1g+3] = f2tf32(ra1.w);
    Bs[0][r0g][c0g+0] = f2tf32(rb0.x); Bs[0][r0g][c0g+1] = f2tf32(rb0.y);
    Bs[0][r0g][c0g+2] = f2tf32(rb0.z); Bs[0][r0g][c0g+3] = f2tf32(rb0.w);
    Bs[0][r1g][c1g+0] = f2tf32(rb1.x); Bs[0][r1g][c1g+1] = f2tf32(rb1.y);
    Bs[0][r1g][c1g+2] = f2tf32(rb1.z); Bs[0][r1g][c1g+3] = f2tf32(rb1.w);
    __syncthreads();

    const int NC = Kk / KC;
    // prefetch chunk 1
    if (NC > 1) {
        ra0 = *(const float4*)(Ap0 + KC);  ra1 = *(const float4*)(Ap1 + KC);
        rb0 = *(const float4*)(Bp0 + KC);  rb1 = *(const float4*)(Bp1 + KC);
    }

    for (int kc = 0; kc < NC; kc++) {
        const int cur = kc & 1;
        const int nxt = cur ^ 1;

        // store prefetched chunk kc+1 into stage nxt
        if (kc + 1 < NC) {
            As[nxt][r0g][c0g+0] = f2tf32(ra0.x); As[nxt][r0g][c0g+1] = f2tf32(ra0.y);
            As[nxt][r0g][c0g+2] = f2tf32(ra0.z); As[nxt][r0g][c0g+3] = f2tf32(ra0.w);
            As[nxt][r1g][c1g+0] = f2tf32(ra1.x); As[nxt][r1g][c1g+1] = f2tf32(ra1.y);
            As[nxt][r1g][c1g+2] = f2tf32(ra1.z); As[nxt][r1g][c1g+3] = f2tf32(ra1.w);
            Bs[nxt][r0g][c0g+0] = f2tf32(rb0.x); Bs[nxt][r0g][c0g+1] = f2tf32(rb0.y);
            Bs[nxt][r0g][c0g+2] = f2tf32(rb0.z); Bs[nxt][r0g][c0g+3] = f2tf32(rb0.w);
            Bs[nxt][r1g][c1g+0] = f2tf32(rb1.x); Bs[nxt][r1g][c1g+1] = f2tf32(rb1.y);
            Bs[nxt][r1g][c1g+2] = f2tf32(rb1.z); Bs[nxt][r1g][c1g+3] = f2tf32(rb1.w);
        }
        // issue LDG for chunk kc+2 (hidden under this chunk's MMAs)
        if (kc + 2 < NC) {
            const int kb = (kc + 2) * KC;
            ra0 = *(const float4*)(Ap0 + kb);  ra1 = *(const float4*)(Ap1 + kb);
            rb0 = *(const float4*)(Bp0 + kb);  rb1 = *(const float4*)(Bp1 + kb);
        }

        // compute stage cur
        #pragma unroll
        for (int ks = 0; ks < 2; ks++) {
            const int k0 = ks * 8;
            uint32_t af[4][4], bf[4][2];
            #pragma unroll
            for (int i = 0; i < 4; i++) {
                const int r = warp_m + 16*i + grp;
                af[i][0] = As[cur][r    ][k0 + tig];
                af[i][1] = As[cur][r + 8][k0 + tig];
                af[i][2] = As[cur][r    ][k0 + tig + 4];
                af[i][3] = As[cur][r + 8][k0 + tig + 4];
            }
            #pragma unroll
            for (int j = 0; j < 4; j++) {
                const int n0 = warp_n + 8*j + grp;
                bf[j][0] = Bs[cur][n0][k0 + tig];
                bf[j][1] = Bs[cur][n0][k0 + tig + 4];
            }
            #pragma unroll
            for (int i = 0; i < 4; i++)
                #pragma unroll
                for (int j = 0; j < 4; j++)
                    MMA_TF32(acc[i][j], af[i], bf[j]);
        }
        __syncthreads();
    }

    #pragma unroll
    for (int i = 0; i < 4; i++) {
        const int r0 = bm + warp_m + 16*i + grp;
        #pragma unroll
        for (int j = 0; j < 4; j++) {
            const int cn = bn + warp_n + 8*j + 2*tig;
            *(float2*)(C + (size_t)r0 * Nn + cn)       = make_float2(acc[i][j][0], acc[i][j][1]);
            *(float2*)(C + (size_t)(r0 + 8) * Nn + cn) = make_float2(acc[i][j][2], acc[i][j][3]);
        }
    }
}

// ================= RoPE apply + split qkv -> q,k,v [B,H,S,D] ===============
__global__ void rope_split_kernel() {
    int idx = blockIdx.x * 256 + threadIdx.x;   // BB*SS*HH*32 total
    const int i = idx & 31;
    const int h = (idx >> 5) & 15;
    const int s = (idx >> 9) & (SS - 1);
    const int b = idx >> 20;
    const float c  = g_cos[(s << 5) + i];
    const float sn = g_sin[(s << 5) + i];
    const float* row = g_qkv + (size_t)(b * SS + s) * (3 * EE);
    const float2 qp = ((const float2*)(row          ))[(h << 5) + i];
    const float2 kp = ((const float2*)(row +     EE))[(h << 5) + i];
    const float2 vp = ((const float2*)(row + 2 * EE))[(h << 5) + i];
    const size_t base2 = (size_t)((b * HH + h) * SS + s) * 32 + i;
    ((float2*)g_q)[base2] = make_float2(qp.x * c - qp.y * sn, qp.x * sn + qp.y * c);
    ((float2*)g_k)[base2] = make_float2(kp.x * c - kp.y * sn, kp.x * sn + kp.y * c);
    ((float2*)g_v)[base2] = vp;
}

// ================= TF32 tensor-core causal flash, Bq=128 Bk=64 =============
// 8 warps; warp w owns q-rows 128*tq + 16w .. +15 (m16), full n=64 keys/dims.
// S/P acc layout (m16n8): thread(grp,tig) rows {grp,grp+8}, cols {2tig,2tig+1}.
#define FKS 68   // K/V smem row stride (uint32): conflict-free fragment banks

__global__ void __launch_bounds__(256, 2)
flash_tc_kernel() {
    const int tq = (int)gridDim.x - 1 - (int)blockIdx.x;  // big tiles first
    const int bh = blockIdx.y;
    const int b = bh >> 4, h = bh & 15;
    const int tid = threadIdx.x;
    const int wid = tid >> 5;
    const int lane = tid & 31;
    const int grp = lane >> 2;          // 0..7
    const int tig = lane & 3;           // 0..3

    __shared__ __align__(16) uint32_t Ksm[64][FKS];
    __shared__ __align__(16) uint32_t Vsm[64][FKS];

    // ---- Q fragments in registers (scaled by 1/8, tf32) ----
    uint32_t qf[8][4];
    {
        const float* q0 = g_q + ((size_t)bh * SS + 128*tq + 16*wid) * DD;
        #pragma unroll
        for (int kg = 0; kg < 8; kg++) {
            qf[kg][0] = f2tf32(q0[(size_t)grp * DD       + 8*kg + tig    ] * 0.125f);
            qf[kg][1] = f2tf32(q0[(size_t)(grp+8) * DD   + 8*kg + tig    ] * 0.125f);
            qf[kg][2] = f2tf32(q0[(size_t)grp * DD       + 8*kg + tig + 4] * 0.125f);
            qf[kg][3] = f2tf32(q0[(size_t)(grp+8) * DD   + 8*kg + tig + 4] * 0.125f);
        }
    }

    float o[8][4];
    #pragma unroll
    for (int j = 0; j < 8; j++)
        #pragma unroll
        for (int e = 0; e < 4; e++) o[j][e] = 0.f;
    float m0 = -1e30f, m1 = -1e30f, l0 = 0.f, l1 = 0.f;

    const int qrow0 = 128*tq + 16*wid + grp;
    const int qrow1 = qrow0 + 8;

    const int nkt = 2*tq + 2;
    for (int kt = 0; kt < nkt; kt++) {
        __syncthreads();   // prior PV reads of Vsm complete
        // ---- load K and V tiles (64x64) as tf32 ----
        {
            const float* kb = g_k + ((size_t)bh * SS + (size_t)64*kt) * DD;
            const float* vb = g_v + ((size_t)bh * SS + (size_t)64*kt) * DD;
            #pragma unroll
            for (int i = 0; i < 4; i++) {
                const int f = i*256 + tid;
                const int r = f >> 4;
                const int c = (f & 15) << 2;
                const float4 k4 = *(const float4*)(kb + (size_t)r * DD + c);
                const float4 v4 = *(const float4*)(vb + (size_t)r * DD + c);
                uint4 ku = make_uint4(f2tf32(k4.x), f2tf32(k4.y), f2tf32(k4.z), f2tf32(k4.w));
                uint4 vu = make_uint4(f2tf32(v4.x), f2tf32(v4.y), f2tf32(v4.z), f2tf32(v4.w));
                *(uint4*)(&Ksm[r][c]) = ku;
                *(uint4*)(&Vsm[r][c]) = vu;
            }
        }
        __syncthreads();

        // ---- S = Q K^T  (64 MMAs: 8 k-groups x 8 n-frags) ----
        float s[8][4];
        #pragma unroll
        for (int j = 0; j < 8; j++)
            #pragma unroll
            for (int e = 0; e < 4; e++) s[j][e] = 0.f;

        #pragma unroll
        for (int kg = 0; kg < 8; kg++) {
            const int k0 = 8*kg;
            #pragma unroll
            for (int j = 0; j < 8; j++) {
                uint32_t bfr[2];
                bfr[0] = Ksm[8*j + grp][k0 + tig];
                bfr[1] = Ksm[8*j + grp][k0 + tig + 4];
                MMA_TF32(s[j], qf[kg], bfr);
            }
        }

        // ---- causal mask (only last two k-tiles can touch the diagonal) ----
        if (kt >= 2*tq) {
            #pragma unroll
            for (int j = 0; j < 8; j++) {
                const int kc = 64*kt + 8*j + 2*tig;
                if (kc     > qrow0) s[j][0] = -1e30f;
                if (kc + 1 > qrow0) s[j][1] = -1e30f;
                if (kc     > qrow1) s[j][2] = -1e30f;
                if (kc + 1 > qrow1) s[j][3] = -1e30f;
            }
        }

        // ---- online softmax (rows grp / grp+8; quad shfl reductions) ----
        float mx0 = -1e30f, mx1 = -1e30f;
        #pragma unroll
        for (int j = 0; j < 8; j++) {
            mx0 = fmaxf(mx0, fmaxf(s[j][0], s[j][1]));
            mx1 = fmaxf(mx1, fmaxf(s[j][2], s[j][3]));
        }
        mx0 = fmaxf(mx0, __shfl_xor_sync(0xffffffffu, mx0, 1));
        mx0 = fmaxf(mx0, __shfl_xor_sync(0xffffffffu, mx0, 2));
        mx1 = fmaxf(mx1, __shfl_xor_sync(0xffffffffu, mx1, 1));
        mx1 = fmaxf(mx1, __shfl_xor_sync(0xffffffffu, mx1, 2));
        const float mn0 = fmaxf(m0, mx0);
        const float mn1 = fmaxf(m1, mx1);
        const float a0 = __expf(m0 - mn0);
        const float a1 = __expf(m1 - mn1);
        m0 = mn0; m1 = mn1;

        float rs0 = 0.f, rs1 = 0.f;
        #pragma unroll
        for (int j = 0; j < 8; j++) {
            s[j][0] = __expf(s[j][0] - mn0);
            s[j][1] = __expf(s[j][1] - mn0);
            s[j][2] = __expf(s[j][2] - mn1);
            s[j][3] = __expf(s[j][3] - mn1);
            rs0 += s[j][0] + s[j][1];
            rs1 += s[j][2] + s[j][3];
        }
        rs0 += __shfl_xor_sync(0xffffffffu, rs0, 1);
        rs0 += __shfl_xor_sync(0xffffffffu, rs0, 2);
        rs1 += __shfl_xor_sync(0xffffffffu, rs1, 1);
        rs1 += __shfl_xor_sync(0xffffffffu, rs1, 2);
        l0 = l0 * a0 + rs0;
        l1 = l1 * a1 + rs1;

        #pragma unroll
        for (int j = 0; j < 8; j++) {
            o[j][0] *= a0; o[j][1] *= a0;
            o[j][2] *= a1; o[j][3] *= a1;
        }

        // ---- O += P V  (register shfl relayout of P into A-fragments) ----
        const int base4 = grp << 2;
        const int src1 = base4 + (tig >> 1);
        const int src2 = src1 + 2;
        const bool oddt = (tig & 1);
        #pragma unroll
        for (int kg = 0; kg < 8; kg++) {
            const float s1c0 = __shfl_sync(0xffffffffu, s[kg][0], src1);
            const float s1c1 = __shfl_sync(0xffffffffu, s[kg][1], src1);
            const float s1c2 = __shfl_sync(0xffffffffu, s[kg][2], src1);
            const float s1c3 = __shfl_sync(0xffffffffu, s[kg][3], src1);
            const float s2c0 = __shfl_sync(0xffffffffu, s[kg][0], src2);
            const float s2c1 = __shfl_sync(0xffffffffu, s[kg][1], src2);
            const float s2c2 = __shfl_sync(0xffffffffu, s[kg][2], src2);
            const float s2c3 = __shfl_sync(0xffffffffu, s[kg][3], src2);
            uint32_t af[4];
            af[0] = f2tf32(oddt ? s1c1 : s1c0);
            af[1] = f2tf32(oddt ? s1c3 : s1c2);
            af[2] = f2tf32(oddt ? s2c1 : s2c0);
            af[3] = f2tf32(oddt ? s2c3 : s2c2);
            const int k0 = 8*kg;
            #pragma unroll
            for (int j = 0; j < 8; j++) {
                uint32_t bfr[2];
                bfr[0] = Vsm[k0 + tig    ][8*j + grp];
                bfr[1] = Vsm[k0 + tig + 4][8*j + grp];
                MMA_TF32(o[j], af, bfr);
            }
        }
    }

    // ---- epilogue: normalize and write head slice of g_y ----
    const float inv0 = 1.f / l0;
    const float inv1 = 1.f / l1;
    float* y0 = g_y + ((size_t)b * SS + qrow0) * EE + h * DD;
    float* y1 = g_y + ((size_t)b * SS + qrow1) * EE + h * DD;
    #pragma unroll
    for (int j = 0; j < 8; j++) {
        const int cn = 8*j + 2*tig;
        *(float2*)(y0 + cn) = make_float2(o[j][0]*inv0, o[j][1]*inv0);
        *(float2*)(y1 + cn) = make_float2(o[j][2]*inv1, o[j][3]*inv1);
    }
}

// ================= launch ==================================================
extern "C" void kernel_launch(void* const* d_in, const int* in_sizes, int n_in,
                              void* d_out, int out_size) {
    (void)in_sizes; (void)n_in; (void)out_size;
    const float* x    = (const float*)d_in[0];
    const float* Wqkv = (const float*)d_in[1];
    const float* Wo   = (const float*)d_in[2];
    float* out = (float*)d_out;

    rope_tables_kernel<<<(SS*32 + 255)/256, 256>>>();
    // x @ Wqkv^T -> g_qkv   (M=4096, N=3072, K=1024)
    tf32_gemm<false, true><<<dim3(3*EE/128, MROWS/128), 256>>>(x, Wqkv, nullptr, 3*EE, EE);
    rope_split_kernel<<<(BB*SS*HH*32)/256, 256>>>();
    flash_tc_kernel<<<dim3(SS/128, BB*HH), 256>>>();
    // g_y @ Wo^T -> out     (M=4096, N=1024, K=1024)
    tf32_gemm<true, false><<<dim3(EE/128, MROWS/128), 256>>>(nullptr, Wo, out, EE, EE);
}

// round 15
// speedup vs baseline: 2.9280x; 1.0822x over previous
#include <cuda_runtime.h>
#include <math.h>
#include <stdint.h>

#define BB 2
#define SS 2048
#define EE 1024
#define HH 16
#define DD 64
#define MROWS (BB*SS)          // 4096

// ---- scratch (device globals: allocation-free rule) ----
__device__ float g_qkv[(size_t)MROWS * 3 * EE];      // 50.3 MB
__device__ float g_q[(size_t)BB * HH * SS * DD];     // 16.8 MB
__device__ float g_k[(size_t)BB * HH * SS * DD];
__device__ float g_v[(size_t)BB * HH * SS * DD];
__device__ float g_y[(size_t)MROWS * EE];            // tf32-rounded bits (from flash)
__device__ float g_cos[SS * (DD/2)];
__device__ float g_sin[SS * (DD/2)];
// tf32-pre-rounded operands
__device__ uint32_t g_xr[(size_t)MROWS * EE];        // 16.8 MB
__device__ uint32_t g_wqkvr[(size_t)3 * EE * EE];    // 12.6 MB
__device__ uint32_t g_wor[(size_t)EE * EE];          // 4.2 MB

// ================= PTX helpers =============================================
__device__ __forceinline__ uint32_t f2tf32(float x) {
    uint32_t r;
    asm("cvt.rna.tf32.f32 %0, %1;" : "=r"(r) : "f"(x));
    return r;
}
__device__ __forceinline__ uint32_t smem_u32(const void* p) {
    uint32_t a;
    asm("{ .reg .u64 t; cvta.to.shared.u64 t, %1; cvt.u32.u64 %0, t; }"
        : "=r"(a) : "l"(p));
    return a;
}
#define CP_ASYNC16(dst, src) \
    asm volatile("cp.async.cg.shared.global [%0], [%1], 16;" \
                 :: "r"(dst), "l"(src) : "memory")
#define CP_COMMIT() asm volatile("cp.async.commit_group;" ::: "memory")
#define CP_WAIT1()  asm volatile("cp.async.wait_group 1;" ::: "memory")
#define CP_WAIT0()  asm volatile("cp.async.wait_group 0;" ::: "memory")
#define MMA_TF32(c, a, b) \
    asm volatile("mma.sync.aligned.m16n8k8.row.col.f32.tf32.tf32.f32 " \
                 "{%0,%1,%2,%3},{%4,%5,%6,%7},{%8,%9},{%0,%1,%2,%3};" \
                 : "+f"((c)[0]), "+f"((c)[1]), "+f"((c)[2]), "+f"((c)[3]) \
                 : "r"((a)[0]), "r"((a)[1]), "r"((a)[2]), "r"((a)[3]), \
                   "r"((b)[0]), "r"((b)[1]))

// ================= RoPE tables =============================================
__global__ void rope_tables_kernel() {
    int idx = blockIdx.x * blockDim.x + threadIdx.x;   // SS*32 threads
    if (idx >= SS * 32) return;
    int i = idx & 31;
    int s = idx >> 5;
    float theta = (float)exp(-2.0 * (double)i / 64.0 * log(10000.0));
    float freq  = (float)s * theta;
    double fr = (double)freq;
    g_cos[idx] = (float)cos(fr);
    g_sin[idx] = (float)sin(fr);
}

// ================= pre-round x / Wqkv / Wo to TF32 bits ====================
#define NX4  ((MROWS*EE)/4)        // 1048576
#define NW14 ((3*EE*EE)/4)         // 786432
#define NW24 ((EE*EE)/4)           // 262144
__global__ void preconv_kernel(const float* __restrict__ x,
                               const float* __restrict__ wqkv,
                               const float* __restrict__ wo) {
    const int i4 = blockIdx.x * 256 + threadIdx.x;   // 0 .. NX4+NW14+NW24-1
    const float4* src;
    uint32_t* dst;
    int off;
    if (i4 < NX4)             { src = (const float4*)x;    dst = g_xr;    off = i4; }
    else if (i4 < NX4 + NW14) { src = (const float4*)wqkv; dst = g_wqkvr; off = i4 - NX4; }
    else                      { src = (const float4*)wo;   dst = g_wor;   off = i4 - NX4 - NW14; }
    const float4 v = src[off];
    uint4 u;
    u.x = f2tf32(v.x); u.y = f2tf32(v.y); u.z = f2tf32(v.z); u.w = f2tf32(v.w);
    *(uint4*)(dst + (size_t)off * 4) = u;
}

// ================= TF32 mma.sync GEMM (NT): C[m,n]=sum_k A[m,k]*B[n,k] =====
// Operands are PRE-ROUNDED tf32 bits in global. Fill via cp.async (2 stages).
// CTA tile 128x128, 8 warps in 2(m) x 4(n), warp tile 64x32, K-chunk 16.
#define KC 16
#define SMS 20          // smem row stride (u32): 80B = 5x16B (cp.async aligned)
#define STAGE_BYTES (128*SMS*4)   // 10240

template<bool G2>
__global__ void __launch_bounds__(256, 2)
tf32_gemm(float* __restrict__ Cparam, int Nn, int Kk) {
    const uint32_t* A = G2 ? (const uint32_t*)g_y : g_xr;
    const uint32_t* B = G2 ? g_wor : g_wqkvr;
    float*          C = G2 ? Cparam : g_qkv;

    __shared__ uint32_t As[2][128][SMS];
    __shared__ uint32_t Bs[2][128][SMS];

    const int tid = threadIdx.x;
    const int wid = tid >> 5;
    const int lane = tid & 31;
    const int grp = lane >> 2;          // 0..7
    const int tig = lane & 3;           // 0..3
    const int warp_m = (wid & 1) * 64;
    const int warp_n = (wid >> 1) * 32;
    const int bm = blockIdx.y * 128;
    const int bn = blockIdx.x * 128;

    const int r0g = (2*tid + 0) >> 2, c0g = ((2*tid + 0) & 3) * 4;
    const int r1g = (2*tid + 1) >> 2, c1g = ((2*tid + 1) & 3) * 4;
    const uint32_t* a0 = A + (size_t)(bm + r0g) * Kk + c0g;
    const uint32_t* a1 = A + (size_t)(bm + r1g) * Kk + c1g;
    const uint32_t* b0 = B + (size_t)(bn + r0g) * Kk + c0g;
    const uint32_t* b1 = B + (size_t)(bn + r1g) * Kk + c1g;
    const uint32_t da0 = smem_u32(&As[0][r0g][c0g]);
    const uint32_t da1 = smem_u32(&As[0][r1g][c1g]);
    const uint32_t db0 = smem_u32(&Bs[0][r0g][c0g]);
    const uint32_t db1 = smem_u32(&Bs[0][r1g][c1g]);

    float acc[4][4][4];
    #pragma unroll
    for (int i = 0; i < 4; i++)
        #pragma unroll
        for (int j = 0; j < 4; j++)
            #pragma unroll
            for (int e = 0; e < 4; e++) acc[i][j][e] = 0.f;

    // prologue: chunk 0 -> stage 0
    CP_ASYNC16(da0, a0); CP_ASYNC16(da1, a1);
    CP_ASYNC16(db0, b0); CP_ASYNC16(db1, b1);
    CP_COMMIT();

    const int NC = Kk / KC;
    for (int kc = 0; kc < NC; kc++) {
        if (kc + 1 < NC) {
            const int kb = (kc + 1) * KC;
            const uint32_t so = (uint32_t)((kc + 1) & 1) * STAGE_BYTES;
            CP_ASYNC16(da0 + so, a0 + kb); CP_ASYNC16(da1 + so, a1 + kb);
            CP_ASYNC16(db0 + so, b0 + kb); CP_ASYNC16(db1 + so, b1 + kb);
            CP_COMMIT();
            CP_WAIT1();            // chunk kc has landed
        } else {
            CP_WAIT0();
        }
        __syncthreads();

        const int cur = kc & 1;
        #pragma unroll
        for (int ks = 0; ks < 2; ks++) {
            const int k0 = ks * 8;
            uint32_t af[4][4], bf[4][2];
            #pragma unroll
            for (int i = 0; i < 4; i++) {
                const int r = warp_m + 16*i + grp;
                af[i][0] = As[cur][r    ][k0 + tig];
                af[i][1] = As[cur][r + 8][k0 + tig];
                af[i][2] = As[cur][r    ][k0 + tig + 4];
                af[i][3] = As[cur][r + 8][k0 + tig + 4];
            }
            #pragma unroll
            for (int j = 0; j < 4; j++) {
                const int n0 = warp_n + 8*j + grp;
                bf[j][0] = Bs[cur][n0][k0 + tig];
                bf[j][1] = Bs[cur][n0][k0 + tig + 4];
            }
            #pragma unroll
            for (int i = 0; i < 4; i++)
                #pragma unroll
                for (int j = 0; j < 4; j++)
                    MMA_TF32(acc[i][j], af[i], bf[j]);
        }
        __syncthreads();   // stage kc&1 free for reuse by chunk kc+2
    }

    #pragma unroll
    for (int i = 0; i < 4; i++) {
        const int r0 = bm + warp_m + 16*i + grp;
        #pragma unroll
        for (int j = 0; j < 4; j++) {
            const int cn = bn + warp_n + 8*j + 2*tig;
            *(float2*)(C + (size_t)r0 * Nn + cn)       = make_float2(acc[i][j][0], acc[i][j][1]);
            *(float2*)(C + (size_t)(r0 + 8) * Nn + cn) = make_float2(acc[i][j][2], acc[i][j][3]);
        }
    }
}

// ================= RoPE apply + split qkv -> q,k,v [B,H,S,D] ===============
__global__ void rope_split_kernel() {
    int idx = blockIdx.x * 256 + threadIdx.x;   // BB*SS*HH*32 total
    const int i = idx & 31;
    const int h = (idx >> 5) & 15;
    const int s = (idx >> 9) & (SS - 1);
    const int b = idx >> 20;
    const float c  = g_cos[(s << 5) + i];
    const float sn = g_sin[(s << 5) + i];
    const float* row = g_qkv + (size_t)(b * SS + s) * (3 * EE);
    const float2 qp = ((const float2*)(row          ))[(h << 5) + i];
    const float2 kp = ((const float2*)(row +     EE))[(h << 5) + i];
    const float2 vp = ((const float2*)(row + 2 * EE))[(h << 5) + i];
    const size_t base2 = (size_t)((b * HH + h) * SS + s) * 32 + i;
    ((float2*)g_q)[base2] = make_float2(qp.x * c - qp.y * sn, qp.x * sn + qp.y * c);
    ((float2*)g_k)[base2] = make_float2(kp.x * c - kp.y * sn, kp.x * sn + kp.y * c);
    ((float2*)g_v)[base2] = vp;
}

// ================= TF32 tensor-core causal flash, Bq=128 Bk=64 =============
// 8 warps; warp w owns q-rows 128*tq + 16w .. +15 (m16), full n=64 keys/dims.
// S/P acc layout (m16n8): thread(grp,tig) rows {grp,grp+8}, cols {2tig,2tig+1}.
#define FKS 68   // K/V smem row stride (uint32): conflict-free fragment banks

__global__ void __launch_bounds__(256, 2)
flash_tc_kernel() {
    const int tq = (int)gridDim.x - 1 - (int)blockIdx.x;  // big tiles first
    const int bh = blockIdx.y;
    const int b = bh >> 4, h = bh & 15;
    const int tid = threadIdx.x;
    const int wid = tid >> 5;
    const int lane = tid & 31;
    const int grp = lane >> 2;          // 0..7
    const int tig = lane & 3;           // 0..3

    __shared__ __align__(16) uint32_t Ksm[64][FKS];
    __shared__ __align__(16) uint32_t Vsm[64][FKS];

    // ---- Q fragments in registers (scaled by 1/8, tf32) ----
    uint32_t qf[8][4];
    {
        const float* q0 = g_q + ((size_t)bh * SS + 128*tq + 16*wid) * DD;
        #pragma unroll
        for (int kg = 0; kg < 8; kg++) {
            qf[kg][0] = f2tf32(q0[(size_t)grp * DD       + 8*kg + tig    ] * 0.125f);
            qf[kg][1] = f2tf32(q0[(size_t)(grp+8) * DD   + 8*kg + tig    ] * 0.125f);
            qf[kg][2] = f2tf32(q0[(size_t)grp * DD       + 8*kg + tig + 4] * 0.125f);
            qf[kg][3] = f2tf32(q0[(size_t)(grp+8) * DD   + 8*kg + tig + 4] * 0.125f);
        }
    }

    float o[8][4];
    #pragma unroll
    for (int j = 0; j < 8; j++)
        #pragma unroll
        for (int e = 0; e < 4; e++) o[j][e] = 0.f;
    float m0 = -1e30f, m1 = -1e30f, l0 = 0.f, l1 = 0.f;

    const int qrow0 = 128*tq + 16*wid + grp;
    const int qrow1 = qrow0 + 8;

    const int nkt = 2*tq + 2;
    for (int kt = 0; kt < nkt; kt++) {
        __syncthreads();   // prior PV reads of Vsm complete
        // ---- load K and V tiles (64x64) as tf32 ----
        {
            const float* kb = g_k + ((size_t)bh * SS + (size_t)64*kt) * DD;
            const float* vb = g_v + ((size_t)bh * SS + (size_t)64*kt) * DD;
            #pragma unroll
            for (int i = 0; i < 4; i++) {
                const int f = i*256 + tid;
                const int r = f >> 4;
                const int c = (f & 15) << 2;
                const float4 k4 = *(const float4*)(kb + (size_t)r * DD + c);
                const float4 v4 = *(const float4*)(vb + (size_t)r * DD + c);
                uint4 ku = make_uint4(f2tf32(k4.x), f2tf32(k4.y), f2tf32(k4.z), f2tf32(k4.w));
                uint4 vu = make_uint4(f2tf32(v4.x), f2tf32(v4.y), f2tf32(v4.z), f2tf32(v4.w));
                *(uint4*)(&Ksm[r][c]) = ku;
                *(uint4*)(&Vsm[r][c]) = vu;
            }
        }
        __syncthreads();

        // ---- S = Q K^T ----
        float s[8][4];
        #pragma unroll
        for (int j = 0; j < 8; j++)
            #pragma unroll
            for (int e = 0; e < 4; e++) s[j][e] = 0.f;

        #pragma unroll
        for (int kg = 0; kg < 8; kg++) {
            const int k0 = 8*kg;
            #pragma unroll
            for (int j = 0; j < 8; j++) {
                uint32_t bfr[2];
                bfr[0] = Ksm[8*j + grp][k0 + tig];
                bfr[1] = Ksm[8*j + grp][k0 + tig + 4];
                MMA_TF32(s[j], qf[kg], bfr);
            }
        }

        // ---- causal mask ----
        if (kt >= 2*tq) {
            #pragma unroll
            for (int j = 0; j < 8; j++) {
                const int kc = 64*kt + 8*j + 2*tig;
                if (kc     > qrow0) s[j][0] = -1e30f;
                if (kc + 1 > qrow0) s[j][1] = -1e30f;
                if (kc     > qrow1) s[j][2] = -1e30f;
                if (kc + 1 > qrow1) s[j][3] = -1e30f;
            }
        }

        // ---- online softmax ----
        float mx0 = -1e30f, mx1 = -1e30f;
        #pragma unroll
        for (int j = 0; j < 8; j++) {
            mx0 = fmaxf(mx0, fmaxf(s[j][0], s[j][1]));
            mx1 = fmaxf(mx1, fmaxf(s[j][2], s[j][3]));
        }
        mx0 = fmaxf(mx0, __shfl_xor_sync(0xffffffffu, mx0, 1));
        mx0 = fmaxf(mx0, __shfl_xor_sync(0xffffffffu, mx0, 2));
        mx1 = fmaxf(mx1, __shfl_xor_sync(0xffffffffu, mx1, 1));
        mx1 = fmaxf(mx1, __shfl_xor_sync(0xffffffffu, mx1, 2));
        const float mn0 = fmaxf(m0, mx0);
        const float mn1 = fmaxf(m1, mx1);
        const float a0 = __expf(m0 - mn0);
        const float a1 = __expf(m1 - mn1);
        m0 = mn0; m1 = mn1;

        float rs0 = 0.f, rs1 = 0.f;
        #pragma unroll
        for (int j = 0; j < 8; j++) {
            s[j][0] = __expf(s[j][0] - mn0);
            s[j][1] = __expf(s[j][1] - mn0);
            s[j][2] = __expf(s[j][2] - mn1);
            s[j][3] = __expf(s[j][3] - mn1);
            rs0 += s[j][0] + s[j][1];
            rs1 += s[j][2] + s[j][3];
        }
        rs0 += __shfl_xor_sync(0xffffffffu, rs0, 1);
        rs0 += __shfl_xor_sync(0xffffffffu, rs0, 2);
        rs1 += __shfl_xor_sync(0xffffffffu, rs1, 1);
        rs1 += __shfl_xor_sync(0xffffffffu, rs1, 2);
        l0 = l0 * a0 + rs0;
        l1 = l1 * a1 + rs1;

        #pragma unroll
        for (int j = 0; j < 8; j++) {
            o[j][0] *= a0; o[j][1] *= a0;
            o[j][2] *= a1; o[j][3] *= a1;
        }

        // ---- O += P V (register shfl relayout) ----
        const int base4 = grp << 2;
        const int src1 = base4 + (tig >> 1);
        const int src2 = src1 + 2;
        const bool oddt = (tig & 1);
        #pragma unroll
        for (int kg = 0; kg < 8; kg++) {
            const float s1c0 = __shfl_sync(0xffffffffu, s[kg][0], src1);
            const float s1c1 = __shfl_sync(0xffffffffu, s[kg][1], src1);
            const float s1c2 = __shfl_sync(0xffffffffu, s[kg][2], src1);
            const float s1c3 = __shfl_sync(0xffffffffu, s[kg][3], src1);
            const float s2c0 = __shfl_sync(0xffffffffu, s[kg][0], src2);
            const float s2c1 = __shfl_sync(0xffffffffu, s[kg][1], src2);
            const float s2c2 = __shfl_sync(0xffffffffu, s[kg][2], src2);
            const float s2c3 = __shfl_sync(0xffffffffu, s[kg][3], src2);
            uint32_t af[4];
            af[0] = f2tf32(oddt ? s1c1 : s1c0);
            af[1] = f2tf32(oddt ? s1c3 : s1c2);
            af[2] = f2tf32(oddt ? s2c1 : s2c0);
            af[3] = f2tf32(oddt ? s2c3 : s2c2);
            const int k0 = 8*kg;
            #pragma unroll
            for (int j = 0; j < 8; j++) {
                uint32_t bfr[2];
                bfr[0] = Vsm[k0 + tig    ][8*j + grp];
                bfr[1] = Vsm[k0 + tig + 4][8*j + grp];
                MMA_TF32(o[j], af, bfr);
            }
        }
    }

    // ---- epilogue: normalize and write g_y PRE-ROUNDED to tf32 bits ----
    const float inv0 = 1.f / l0;
    const float inv1 = 1.f / l1;
    float* y0 = g_y + ((size_t)b * SS + qrow0) * EE + h * DD;
    float* y1 = g_y + ((size_t)b * SS + qrow1) * EE + h * DD;
    #pragma unroll
    for (int j = 0; j < 8; j++) {
        const int cn = 8*j + 2*tig;
        *(float2*)(y0 + cn) = make_float2(__uint_as_float(f2tf32(o[j][0]*inv0)),
                                          __uint_as_float(f2tf32(o[j][1]*inv0)));
        *(float2*)(y1 + cn) = make_float2(__uint_as_float(f2tf32(o[j][2]*inv1)),
                                          __uint_as_float(f2tf32(o[j][3]*inv1)));
    }
}

// ================= launch ==================================================
extern "C" void kernel_launch(void* const* d_in, const int* in_sizes, int n_in,
                              void* d_out, int out_size) {
    (void)in_sizes; (void)n_in; (void)out_size;
    const float* x    = (const float*)d_in[0];
    const float* Wqkv = (const float*)d_in[1];
    const float* Wo   = (const float*)d_in[2];
    float* out = (float*)d_out;

    preconv_kernel<<<(NX4 + NW14 + NW24) / 256, 256>>>(x, Wqkv, Wo);
    rope_tables_kernel<<<(SS*32 + 255)/256, 256>>>();
    // x @ Wqkv^T -> g_qkv   (M=4096, N=3072, K=1024)
    tf32_gemm<false><<<dim3(3*EE/128, MROWS/128), 256>>>(nullptr, 3*EE, EE);
    rope_split_kernel<<<(BB*SS*HH*32)/256, 256>>>();
    flash_tc_kernel<<<dim3(SS/128, BB*HH), 256>>>();
    // g_y @ Wo^T -> out     (M=4096, N=1024, K=1024)
    tf32_gemm<true><<<dim3(EE/128, MROWS/128), 256>>>(out, EE, EE);
}

// round 16
// speedup vs baseline: 2.9999x; 1.0246x over previous
#include <cuda_runtime.h>
#include <math.h>
#include <stdint.h>

#define BB 2
#define SS 2048
#define EE 1024
#define HH 16
#define DD 64
#define MROWS (BB*SS)          // 4096

// ---- scratch (device globals: allocation-free rule) ----
__device__ float g_qkv[(size_t)MROWS * 3 * EE];      // 50.3 MB
__device__ float g_q[(size_t)BB * HH * SS * DD];     // fp32
__device__ float g_k[(size_t)BB * HH * SS * DD];     // tf32 bits
__device__ float g_v[(size_t)BB * HH * SS * DD];     // tf32 bits
__device__ float g_y[(size_t)MROWS * EE];            // tf32 bits (from flash)
__device__ float g_cos[SS * (DD/2)];
__device__ float g_sin[SS * (DD/2)];
// tf32-pre-rounded GEMM operands
__device__ uint32_t g_xr[(size_t)MROWS * EE];        // 16.8 MB
__device__ uint32_t g_wqkvr[(size_t)3 * EE * EE];    // 12.6 MB
__device__ uint32_t g_wor[(size_t)EE * EE];          // 4.2 MB

// ================= PTX helpers =============================================
__device__ __forceinline__ uint32_t f2tf32(float x) {
    uint32_t r;
    asm("cvt.rna.tf32.f32 %0, %1;" : "=r"(r) : "f"(x));
    return r;
}
__device__ __forceinline__ uint32_t smem_u32(const void* p) {
    uint32_t a;
    asm("{ .reg .u64 t; cvta.to.shared.u64 t, %1; cvt.u32.u64 %0, t; }"
        : "=r"(a) : "l"(p));
    return a;
}
#define CP_ASYNC16(dst, src) \
    asm volatile("cp.async.cg.shared.global [%0], [%1], 16;" \
                 :: "r"(dst), "l"(src) : "memory")
#define CP_COMMIT() asm volatile("cp.async.commit_group;" ::: "memory")
#define CP_WAIT1()  asm volatile("cp.async.wait_group 1;" ::: "memory")
#define CP_WAIT0()  asm volatile("cp.async.wait_group 0;" ::: "memory")
#define MMA_TF32(c, a, b) \
    asm volatile("mma.sync.aligned.m16n8k8.row.col.f32.tf32.tf32.f32 " \
                 "{%0,%1,%2,%3},{%4,%5,%6,%7},{%8,%9},{%0,%1,%2,%3};" \
                 : "+f"((c)[0]), "+f"((c)[1]), "+f"((c)[2]), "+f"((c)[3]) \
                 : "r"((a)[0]), "r"((a)[1]), "r"((a)[2]), "r"((a)[3]), \
                   "r"((b)[0]), "r"((b)[1]))

// ================= RoPE tables =============================================
__global__ void rope_tables_kernel() {
    int idx = blockIdx.x * blockDim.x + threadIdx.x;   // SS*32 threads
    if (idx >= SS * 32) return;
    int i = idx & 31;
    int s = idx >> 5;
    float theta = (float)exp(-2.0 * (double)i / 64.0 * log(10000.0));
    float freq  = (float)s * theta;
    double fr = (double)freq;
    g_cos[idx] = (float)cos(fr);
    g_sin[idx] = (float)sin(fr);
}

// ================= pre-round x / Wqkv / Wo to TF32 bits ====================
#define NX4  ((MROWS*EE)/4)        // 1048576
#define NW14 ((3*EE*EE)/4)         // 786432
#define NW24 ((EE*EE)/4)           // 262144
__global__ void preconv_kernel(const float* __restrict__ x,
                               const float* __restrict__ wqkv,
                               const float* __restrict__ wo) {
    const int i4 = blockIdx.x * 256 + threadIdx.x;   // 0 .. NX4+NW14+NW24-1
    const float4* src;
    uint32_t* dst;
    int off;
    if (i4 < NX4)             { src = (const float4*)x;    dst = g_xr;    off = i4; }
    else if (i4 < NX4 + NW14) { src = (const float4*)wqkv; dst = g_wqkvr; off = i4 - NX4; }
    else                      { src = (const float4*)wo;   dst = g_wor;   off = i4 - NX4 - NW14; }
    const float4 v = src[off];
    uint4 u;
    u.x = f2tf32(v.x); u.y = f2tf32(v.y); u.z = f2tf32(v.z); u.w = f2tf32(v.w);
    *(uint4*)(dst + (size_t)off * 4) = u;
}

// ================= TF32 mma.sync GEMM (NT): C[m,n]=sum_k A[m,k]*B[n,k] =====
// Operands PRE-ROUNDED tf32 bits in global. cp.async fill, 2 stages.
#define KC 16
#define SMS 20          // smem row stride (u32): 80B = 5x16B (cp.async aligned)
#define STAGE_BYTES (128*SMS*4)   // 10240

template<bool G2>
__global__ void __launch_bounds__(256, 2)
tf32_gemm(float* __restrict__ Cparam, int Nn, int Kk) {
    const uint32_t* A = G2 ? (const uint32_t*)g_y : g_xr;
    const uint32_t* B = G2 ? g_wor : g_wqkvr;
    float*          C = G2 ? Cparam : g_qkv;

    __shared__ uint32_t As[2][128][SMS];
    __shared__ uint32_t Bs[2][128][SMS];

    const int tid = threadIdx.x;
    const int wid = tid >> 5;
    const int lane = tid & 31;
    const int grp = lane >> 2;          // 0..7
    const int tig = lane & 3;           // 0..3
    const int warp_m = (wid & 1) * 64;
    const int warp_n = (wid >> 1) * 32;
    const int bm = blockIdx.y * 128;
    const int bn = blockIdx.x * 128;

    const int r0g = (2*tid + 0) >> 2, c0g = ((2*tid + 0) & 3) * 4;
    const int r1g = (2*tid + 1) >> 2, c1g = ((2*tid + 1) & 3) * 4;
    const uint32_t* a0 = A + (size_t)(bm + r0g) * Kk + c0g;
    const uint32_t* a1 = A + (size_t)(bm + r1g) * Kk + c1g;
    const uint32_t* b0 = B + (size_t)(bn + r0g) * Kk + c0g;
    const uint32_t* b1 = B + (size_t)(bn + r1g) * Kk + c1g;
    const uint32_t da0 = smem_u32(&As[0][r0g][c0g]);
    const uint32_t da1 = smem_u32(&As[0][r1g][c1g]);
    const uint32_t db0 = smem_u32(&Bs[0][r0g][c0g]);
    const uint32_t db1 = smem_u32(&Bs[0][r1g][c1g]);

    float acc[4][4][4];
    #pragma unroll
    for (int i = 0; i < 4; i++)
        #pragma unroll
        for (int j = 0; j < 4; j++)
            #pragma unroll
            for (int e = 0; e < 4; e++) acc[i][j][e] = 0.f;

    CP_ASYNC16(da0, a0); CP_ASYNC16(da1, a1);
    CP_ASYNC16(db0, b0); CP_ASYNC16(db1, b1);
    CP_COMMIT();

    const int NC = Kk / KC;
    for (int kc = 0; kc < NC; kc++) {
        if (kc + 1 < NC) {
            const int kb = (kc + 1) * KC;
            const uint32_t so = (uint32_t)((kc + 1) & 1) * STAGE_BYTES;
            CP_ASYNC16(da0 + so, a0 + kb); CP_ASYNC16(da1 + so, a1 + kb);
            CP_ASYNC16(db0 + so, b0 + kb); CP_ASYNC16(db1 + so, b1 + kb);
            CP_COMMIT();
            CP_WAIT1();
        } else {
            CP_WAIT0();
        }
        __syncthreads();

        const int cur = kc & 1;
        #pragma unroll
        for (int ks = 0; ks < 2; ks++) {
            const int k0 = ks * 8;
            uint32_t af[4][4], bf[4][2];
            #pragma unroll
            for (int i = 0; i < 4; i++) {
                const int r = warp_m + 16*i + grp;
                af[i][0] = As[cur][r    ][k0 + tig];
                af[i][1] = As[cur][r + 8][k0 + tig];
                af[i][2] = As[cur][r    ][k0 + tig + 4];
                af[i][3] = As[cur][r + 8][k0 + tig + 4];
            }
            #pragma unroll
            for (int j = 0; j < 4; j++) {
                const int n0 = warp_n + 8*j + grp;
                bf[j][0] = Bs[cur][n0][k0 + tig];
                bf[j][1] = Bs[cur][n0][k0 + tig + 4];
            }
            #pragma unroll
            for (int i = 0; i < 4; i++)
                #pragma unroll
                for (int j = 0; j < 4; j++)
                    MMA_TF32(acc[i][j], af[i], bf[j]);
        }
        __syncthreads();
    }

    #pragma unroll
    for (int i = 0; i < 4; i++) {
        const int r0 = bm + warp_m + 16*i + grp;
        #pragma unroll
        for (int j = 0; j < 4; j++) {
            const int cn = bn + warp_n + 8*j + 2*tig;
            *(float2*)(C + (size_t)r0 * Nn + cn)       = make_float2(acc[i][j][0], acc[i][j][1]);
            *(float2*)(C + (size_t)(r0 + 8) * Nn + cn) = make_float2(acc[i][j][2], acc[i][j][3]);
        }
    }
}

// ================= RoPE apply + split; K,V stored as TF32 bits =============
__global__ void rope_split_kernel() {
    int idx = blockIdx.x * 256 + threadIdx.x;   // BB*SS*HH*32 total
    const int i = idx & 31;
    const int h = (idx >> 5) & 15;
    const int s = (idx >> 9) & (SS - 1);
    const int b = idx >> 20;
    const float c  = g_cos[(s << 5) + i];
    const float sn = g_sin[(s << 5) + i];
    const float* row = g_qkv + (size_t)(b * SS + s) * (3 * EE);
    const float2 qp = ((const float2*)(row          ))[(h << 5) + i];
    const float2 kp = ((const float2*)(row +     EE))[(h << 5) + i];
    const float2 vp = ((const float2*)(row + 2 * EE))[(h << 5) + i];
    const size_t base2 = (size_t)((b * HH + h) * SS + s) * 32 + i;
    ((float2*)g_q)[base2] = make_float2(qp.x * c - qp.y * sn, qp.x * sn + qp.y * c);
    ((float2*)g_k)[base2] = make_float2(
        __uint_as_float(f2tf32(kp.x * c - kp.y * sn)),
        __uint_as_float(f2tf32(kp.x * sn + kp.y * c)));
    ((float2*)g_v)[base2] = make_float2(
        __uint_as_float(f2tf32(vp.x)),
        __uint_as_float(f2tf32(vp.y)));
}

// ================= TF32 tensor-core causal flash, Bq=128 Bk=64 =============
// cp.async double-buffered K/V tiles (dynamic smem, 4 x 64x68 u32 = 69632B).
#define FKS 68                    // row stride (u32)
#define TILE_U32 (64*FKS)         // 4352

__global__ void __launch_bounds__(256, 2)
flash_tc_kernel() {
    extern __shared__ __align__(16) uint32_t sm[];
    // layout: K stage0 | K stage1 | V stage0 | V stage1
    const int tq = (int)gridDim.x - 1 - (int)blockIdx.x;  // big tiles first
    const int bh = blockIdx.y;
    const int b = bh >> 4, h = bh & 15;
    const int tid = threadIdx.x;
    const int wid = tid >> 5;
    const int lane = tid & 31;
    const int grp = lane >> 2;          // 0..7
    const int tig = lane & 3;           // 0..3

    const uint32_t* kgm = (const uint32_t*)g_k + (size_t)bh * SS * DD;
    const uint32_t* vgm = (const uint32_t*)g_v + (size_t)bh * SS * DD;
    const uint32_t sm_u = smem_u32(sm);

    // per-thread fill coords: 4 x 16B per array per tile
    const int fr[4] = { (0*256+tid) >> 4, (1*256+tid) >> 4, (2*256+tid) >> 4, (3*256+tid) >> 4 };
    const int fc = (tid & 15) << 2;

    // ---- Q fragments in registers (scaled by 1/8, tf32) ----
    uint32_t qf[8][4];
    {
        const float* q0 = g_q + ((size_t)bh * SS + 128*tq + 16*wid) * DD;
        #pragma unroll
        for (int kg = 0; kg < 8; kg++) {
            qf[kg][0] = f2tf32(q0[(size_t)grp * DD       + 8*kg + tig    ] * 0.125f);
            qf[kg][1] = f2tf32(q0[(size_t)(grp+8) * DD   + 8*kg + tig    ] * 0.125f);
            qf[kg][2] = f2tf32(q0[(size_t)grp * DD       + 8*kg + tig + 4] * 0.125f);
            qf[kg][3] = f2tf32(q0[(size_t)(grp+8) * DD   + 8*kg + tig + 4] * 0.125f);
        }
    }

    float o[8][4];
    #pragma unroll
    for (int j = 0; j < 8; j++)
        #pragma unroll
        for (int e = 0; e < 4; e++) o[j][e] = 0.f;
    float m0 = -1e30f, m1 = -1e30f, l0 = 0.f, l1 = 0.f;

    const int qrow0 = 128*tq + 16*wid + grp;
    const int qrow1 = qrow0 + 8;
    const int nkt = 2*tq + 2;

    // ---- prologue: issue tiles 0 and 1 (nkt >= 2 always) ----
    #pragma unroll
    for (int st = 0; st < 2; st++) {
        const uint32_t kd = sm_u + (uint32_t)st * TILE_U32 * 4;
        const uint32_t vd = sm_u + (uint32_t)(2 + st) * TILE_U32 * 4;
        const uint32_t goff = (uint32_t)(64*st) * DD;
        #pragma unroll
        for (int i = 0; i < 4; i++) {
            CP_ASYNC16(kd + (uint32_t)(fr[i]*FKS + fc)*4, kgm + goff + fr[i]*DD + fc);
            CP_ASYNC16(vd + (uint32_t)(fr[i]*FKS + fc)*4, vgm + goff + fr[i]*DD + fc);
        }
        CP_COMMIT();
    }

    for (int kt = 0; kt < nkt; kt++) {
        CP_WAIT1();          // tile kt landed (kt+1 may be in flight)
        __syncthreads();

        const int stage = kt & 1;
        const uint32_t* Ks = sm + (size_t)stage * TILE_U32;
        const uint32_t* Vs = sm + (size_t)(2 + stage) * TILE_U32;

        // ---- S = Q K^T ----
        float s[8][4];
        #pragma unroll
        for (int j = 0; j < 8; j++)
            #pragma unroll
            for (int e = 0; e < 4; e++) s[j][e] = 0.f;

        #pragma unroll
        for (int kg = 0; kg < 8; kg++) {
            const int k0 = 8*kg;
            #pragma unroll
            for (int j = 0; j < 8; j++) {
                uint32_t bfr[2];
                bfr[0] = Ks[(8*j + grp)*FKS + k0 + tig];
                bfr[1] = Ks[(8*j + grp)*FKS + k0 + tig + 4];
                MMA_TF32(s[j], qf[kg], bfr);
            }
        }

        // ---- causal mask ----
        if (kt >= 2*tq) {
            #pragma unroll
            for (int j = 0; j < 8; j++) {
                const int kc = 64*kt + 8*j + 2*tig;
                if (kc     > qrow0) s[j][0] = -1e30f;
                if (kc + 1 > qrow0) s[j][1] = -1e30f;
                if (kc     > qrow1) s[j][2] = -1e30f;
                if (kc + 1 > qrow1) s[j][3] = -1e30f;
            }
        }

        // ---- online softmax ----
        float mx0 = -1e30f, mx1 = -1e30f;
        #pragma unroll
        for (int j = 0; j < 8; j++) {
            mx0 = fmaxf(mx0, fmaxf(s[j][0], s[j][1]));
            mx1 = fmaxf(mx1, fmaxf(s[j][2], s[j][3]));
        }
        mx0 = fmaxf(mx0, __shfl_xor_sync(0xffffffffu, mx0, 1));
        mx0 = fmaxf(mx0, __shfl_xor_sync(0xffffffffu, mx0, 2));
        mx1 = fmaxf(mx1, __shfl_xor_sync(0xffffffffu, mx1, 1));
        mx1 = fmaxf(mx1, __shfl_xor_sync(0xffffffffu, mx1, 2));
        const float mn0 = fmaxf(m0, mx0);
        const float mn1 = fmaxf(m1, mx1);
        const float a0 = __expf(m0 - mn0);
        const float a1 = __expf(m1 - mn1);
        m0 = mn0; m1 = mn1;

        float rs0 = 0.f, rs1 = 0.f;
        #pragma unroll
        for (int j = 0; j < 8; j++) {
            s[j][0] = __expf(s[j][0] - mn0);
            s[j][1] = __expf(s[j][1] - mn0);
            s[j][2] = __expf(s[j][2] - mn1);
            s[j][3] = __expf(s[j][3] - mn1);
            rs0 += s[j][0] + s[j][1];
            rs1 += s[j][2] + s[j][3];
        }
        rs0 += __shfl_xor_sync(0xffffffffu, rs0, 1);
        rs0 += __shfl_xor_sync(0xffffffffu, rs0, 2);
        rs1 += __shfl_xor_sync(0xffffffffu, rs1, 1);
        rs1 += __shfl_xor_sync(0xffffffffu, rs1, 2);
        l0 = l0 * a0 + rs0;
        l1 = l1 * a1 + rs1;

        #pragma unroll
        for (int j = 0; j < 8; j++) {
            o[j][0] *= a0; o[j][1] *= a0;
            o[j][2] *= a1; o[j][3] *= a1;
        }

        // ---- O += P V (register shfl relayout) ----
        const int base4 = grp << 2;
        const int src1 = base4 + (tig >> 1);
        const int src2 = src1 + 2;
        const bool oddt = (tig & 1);
        #pragma unroll
        for (int kg = 0; kg < 8; kg++) {
            const float s1c0 = __shfl_sync(0xffffffffu, s[kg][0], src1);
            const float s1c1 = __shfl_sync(0xffffffffu, s[kg][1], src1);
            const float s1c2 = __shfl_sync(0xffffffffu, s[kg][2], src1);
            const float s1c3 = __shfl_sync(0xffffffffu, s[kg][3], src1);
            const float s2c0 = __shfl_sync(0xffffffffu, s[kg][0], src2);
            const float s2c1 = __shfl_sync(0xffffffffu, s[kg][1], src2);
            const float s2c2 = __shfl_sync(0xffffffffu, s[kg][2], src2);
            const float s2c3 = __shfl_sync(0xffffffffu, s[kg][3], src2);
            uint32_t af[4];
            af[0] = f2tf32(oddt ? s1c1 : s1c0);
            af[1] = f2tf32(oddt ? s1c3 : s1c2);
            af[2] = f2tf32(oddt ? s2c1 : s2c0);
            af[3] = f2tf32(oddt ? s2c3 : s2c2);
            const int k0 = 8*kg;
            #pragma unroll
            for (int j = 0; j < 8; j++) {
                uint32_t bfr[2];
                bfr[0] = Vs[(k0 + tig    )*FKS + 8*j + grp];
                bfr[1] = Vs[(k0 + tig + 4)*FKS + 8*j + grp];
                MMA_TF32(o[j], af, bfr);
            }
        }

        __syncthreads();     // all warps done reading stage -> safe to refill
        if (kt + 2 < nkt) {
            const uint32_t kd = sm_u + (uint32_t)stage * TILE_U32 * 4;
            const uint32_t vd = sm_u + (uint32_t)(2 + stage) * TILE_U32 * 4;
            const uint32_t goff = (uint32_t)(64*(kt+2)) * DD;
            #pragma unroll
            for (int i = 0; i < 4; i++) {
                CP_ASYNC16(kd + (uint32_t)(fr[i]*FKS + fc)*4, kgm + goff + fr[i]*DD + fc);
                CP_ASYNC16(vd + (uint32_t)(fr[i]*FKS + fc)*4, vgm + goff + fr[i]*DD + fc);
            }
        }
        CP_COMMIT();         // commit every iter (possibly empty) to keep counts
    }

    // ---- epilogue: normalize; write g_y PRE-ROUNDED to tf32 bits ----
    const float inv0 = 1.f / l0;
    const float inv1 = 1.f / l1;
    float* y0 = g_y + ((size_t)b * SS + qrow0) * EE + h * DD;
    float* y1 = g_y + ((size_t)b * SS + qrow1) * EE + h * DD;
    #pragma unroll
    for (int j = 0; j < 8; j++) {
        const int cn = 8*j + 2*tig;
        *(float2*)(y0 + cn) = make_float2(__uint_as_float(f2tf32(o[j][0]*inv0)),
                                          __uint_as_float(f2tf32(o[j][1]*inv0)));
        *(float2*)(y1 + cn) = make_float2(__uint_as_float(f2tf32(o[j][2]*inv1)),
                                          __uint_as_float(f2tf32(o[j][3]*inv1)));
    }
}

// ================= launch ==================================================
#define FLASH_SMEM (4 * TILE_U32 * 4)   // 69632 bytes

extern "C" void kernel_launch(void* const* d_in, const int* in_sizes, int n_in,
                              void* d_out, int out_size) {
    (void)in_sizes; (void)n_in; (void)out_size;
    const float* x    = (const float*)d_in[0];
    const float* Wqkv = (const float*)d_in[1];
    const float* Wo   = (const float*)d_in[2];
    float* out = (float*)d_out;

    cudaFuncSetAttribute(flash_tc_kernel,
                         cudaFuncAttributeMaxDynamicSharedMemorySize, FLASH_SMEM);

    preconv_kernel<<<(NX4 + NW14 + NW24) / 256, 256>>>(x, Wqkv, Wo);
    rope_tables_kernel<<<(SS*32 + 255)/256, 256>>>();
    tf32_gemm<false><<<dim3(3*EE/128, MROWS/128), 256>>>(nullptr, 3*EE, EE);
    rope_split_kernel<<<(BB*SS*HH*32)/256, 256>>>();
    flash_tc_kernel<<<dim3(SS/128, BB*HH), 256, FLASH_SMEM>>>();
    tf32_gemm<true><<<dim3(EE/128, MROWS/128), 256>>>(out, EE, EE);
}